// round 11
// baseline (speedup 1.0000x reference)
#include <cuda_runtime.h>
#include <cstdint>

#define BDIM 4
#define SDIM 2048
#define HDIM 1024
#define NH   16
#define DH   64
#define KB   16

// Scratch (device globals: no allocation allowed in kernel_launch)
__device__ float g_Q[(size_t)BDIM * NH * SDIM * DH];
__device__ float g_K[(size_t)BDIM * NH * SDIM * DH];
__device__ float g_V[(size_t)BDIM * NH * SDIM * DH];
__device__ float g_ctx[(size_t)BDIM * SDIM * HDIM];
__device__ float2 g_stats[(size_t)BDIM * NH * SDIM];   // (row_max, 1/row_sum)

// ---------------------------------------------------------------------------
__device__ __forceinline__ float to_tf32(float x) {
    float r;
    asm("cvt.rna.tf32.f32 %0, %1;" : "=f"(r) : "f"(x));
    return r;
}
__device__ __forceinline__ float4 tf32x4(float4 v) {
    return make_float4(to_tf32(v.x), to_tf32(v.y), to_tf32(v.z), to_tf32(v.w));
}
__device__ __forceinline__ void mma_tf32(float* c, const unsigned* a,
                                         const unsigned* b) {
    asm volatile(
        "mma.sync.aligned.m16n8k8.row.col.f32.tf32.tf32.f32 "
        "{%0,%1,%2,%3}, {%4,%5,%6,%7}, {%8,%9}, {%0,%1,%2,%3};\n"
        : "+f"(c[0]), "+f"(c[1]), "+f"(c[2]), "+f"(c[3])
        : "r"(a[0]), "r"(a[1]), "r"(a[2]), "r"(a[3]), "r"(b[0]), "r"(b[1]));
}
__device__ __forceinline__ void cp_async16(void* smem, const void* gmem) {
    unsigned sa = (unsigned)__cvta_generic_to_shared(smem);
    asm volatile("cp.async.cg.shared.global [%0], [%1], 16;"
                 :: "r"(sa), "l"(gmem) : "memory");
}
#define CP_COMMIT() asm volatile("cp.async.commit_group;" ::: "memory")
#define CP_WAIT(n)  asm volatile("cp.async.wait_group %0;" :: "n"(n) : "memory")

// ---------------------------------------------------------------------------
// Dense GEMM: C[M,N] = A[M,K] @ B[N,K]^T + bias. cp.async double-buffered.
// MODE 0: direct row-major C. MODE 1: scatter to [B,H,S,Dh].
// Block tile 128x128, BK=16, 256 threads, 8 warps (4m x 2n), warp tile 32x64.
// Low regs + 41KB smem -> 2 CTAs/SM.
// ---------------------------------------------------------------------------
template <int MODE>
__global__ void __launch_bounds__(256, 2) gemm128(
    const float* __restrict__ A, const float* __restrict__ Bm,
    const float* __restrict__ bias, float* __restrict__ C,
    int K, int ldc)
{
    __shared__ float As[2][128][20];
    __shared__ float Bs[2][128][20];

    const int tid  = threadIdx.x;
    const int wid  = tid >> 5, lane = tid & 31;
    const int wm   = wid >> 1, wn = wid & 1;
    const int g    = lane >> 2, qd = lane & 3;
    const int brow = blockIdx.y * 128;
    const int bcol = blockIdx.x * 128;

    const int lr = tid >> 1;         // 0..127
    const int lc = (tid & 1) * 8;    // 0 or 8

    float acc[2][8][4];
#pragma unroll
    for (int i = 0; i < 2; i++)
#pragma unroll
        for (int j = 0; j < 8; j++)
#pragma unroll
            for (int r = 0; r < 4; r++) acc[i][j][r] = 0.f;

    const float* Ap = A  + (size_t)(brow + lr) * K + lc;
    const float* Bp = Bm + (size_t)(bcol + lr) * K + lc;

    // prologue: tile 0 -> buf 0
    cp_async16(&As[0][lr][lc],     Ap);
    cp_async16(&As[0][lr][lc + 4], Ap + 4);
    cp_async16(&Bs[0][lr][lc],     Bp);
    cp_async16(&Bs[0][lr][lc + 4], Bp + 4);
    CP_COMMIT();

    int buf = 0;
    for (int k0 = 0; k0 < K; k0 += KB, buf ^= 1) {
        const bool more = (k0 + KB) < K;
        if (more) {
            cp_async16(&As[buf ^ 1][lr][lc],     Ap + k0 + KB);
            cp_async16(&As[buf ^ 1][lr][lc + 4], Ap + k0 + KB + 4);
            cp_async16(&Bs[buf ^ 1][lr][lc],     Bp + k0 + KB);
            cp_async16(&Bs[buf ^ 1][lr][lc + 4], Bp + k0 + KB + 4);
            CP_COMMIT();
            CP_WAIT(1);
        } else {
            CP_WAIT(0);
        }
        // in-place RNA-tf32 conversion of own copied data
        {
            float4* a0 = (float4*)&As[buf][lr][lc];
            a0[0] = tf32x4(a0[0]); a0[1] = tf32x4(a0[1]);
            float4* b0 = (float4*)&Bs[buf][lr][lc];
            b0[0] = tf32x4(b0[0]); b0[1] = tf32x4(b0[1]);
        }
        __syncthreads();

#pragma unroll
        for (int ks = 0; ks < 2; ks++) {
            const int kb = ks * 8;
            unsigned a[2][4], b[8][2];
#pragma unroll
            for (int mt = 0; mt < 2; mt++) {
                const int r0 = wm * 32 + mt * 16 + g;
                a[mt][0] = __float_as_uint(As[buf][r0    ][kb + qd]);
                a[mt][1] = __float_as_uint(As[buf][r0 + 8][kb + qd]);
                a[mt][2] = __float_as_uint(As[buf][r0    ][kb + qd + 4]);
                a[mt][3] = __float_as_uint(As[buf][r0 + 8][kb + qd + 4]);
            }
#pragma unroll
            for (int nt = 0; nt < 8; nt++) {
                const int c0 = wn * 64 + nt * 8 + g;
                b[nt][0] = __float_as_uint(Bs[buf][c0][kb + qd]);
                b[nt][1] = __float_as_uint(Bs[buf][c0][kb + qd + 4]);
            }
#pragma unroll
            for (int mt = 0; mt < 2; mt++)
#pragma unroll
                for (int nt = 0; nt < 8; nt++)
                    mma_tf32(acc[mt][nt], a[mt], b[nt]);
        }
        __syncthreads();
    }

#pragma unroll
    for (int mt = 0; mt < 2; mt++) {
#pragma unroll
        for (int nt = 0; nt < 8; nt++) {
            const int cc = bcol + wn * 64 + nt * 8 + 2 * qd;
            const float bx = bias[cc], by = bias[cc + 1];
#pragma unroll
            for (int half = 0; half < 2; half++) {
                const int r = brow + wm * 32 + mt * 16 + g + half * 8;
                float2 v;
                v.x = acc[mt][nt][2 * half]     + bx;
                v.y = acc[mt][nt][2 * half + 1] + by;
                if (MODE == 1) {
                    const int b_ = r / SDIM, s = r % SDIM;
                    const int h  = cc / DH,  d = cc % DH;
                    *(float2*)&C[(((size_t)(b_ * NH + h)) * SDIM + s) * DH + d] = v;
                } else {
                    *(float2*)&C[(size_t)r * ldc + cc] = v;
                }
            }
        }
    }
}

// ---------------------------------------------------------------------------
// Flash attention with cp.async pipelining:
//   K double-buffered (next chunk lands during current compute);
//   V issued at chunk start, waited only before PV (hidden by score MMAs).
// Writes ctx + row stats only. 8 warps, warp = 16 q-rows.
// ---------------------------------------------------------------------------
__global__ void __launch_bounds__(256, 1) flash_attn(
    const int* __restrict__ mask, float* __restrict__ ctx,
    float2* __restrict__ stats)
{
    extern __shared__ char smem_raw[];
    float (*Qs)[68]       = (float(*)[68])smem_raw;                         // 128x64
    float (*Ks)[128][68]  = (float(*)[128][68])(smem_raw + 34816);          // 2x128x64
    float (*Vs)[72]       = (float(*)[72])(smem_raw + 34816 + 69632);       // 128x64
    float (*Ps)[132]      = (float(*)[132])(smem_raw + 34816 + 69632 + 36864);
    int*   Ms             = (int*)(smem_raw + 34816 + 69632 + 36864 + 67584);

    const int bh = blockIdx.y;
    const int q0 = blockIdx.x * 128;
    const int b_ = bh / NH, h = bh % NH;
    const int tid = threadIdx.x, wid = tid >> 5, lane = tid & 31;
    const int g = lane >> 2, qd = lane & 3;
    const int r0 = wid * 16 + g;

    const float* Qg = g_Q + ((size_t)bh * SDIM + q0) * DH;
    const float* Kg = g_K + (size_t)bh * SDIM * DH;
    const float* Vg = g_V + (size_t)bh * SDIM * DH;

    const int ldr = tid >> 4;            // 0..15 base row (+16*i)
    const int ldc_ = (tid & 15) * 4;     // col

    // Stage Q (RNA-tf32) + mask
#pragma unroll
    for (int i = 0; i < 8; i++) {
        const int r = ldr + i * 16;
        *(float4*)&Qs[r][ldc_] = tf32x4(*(const float4*)(Qg + (size_t)r * DH + ldc_));
    }
    for (int i = tid; i < SDIM / 4; i += 256)
        ((int4*)Ms)[i] = ((const int4*)(mask + b_ * SDIM))[i];

    // prologue: K chunk 0 -> Ks[0]
#pragma unroll
    for (int i = 0; i < 8; i++) {
        const int r = ldr + i * 16;
        cp_async16(&Ks[0][r][ldc_], Kg + (size_t)r * DH + ldc_);
    }
    CP_COMMIT();

    float m_lo = -1e30f, m_hi = -1e30f, s_lo = 0.f, s_hi = 0.f;
    float acc_o[8][4];
#pragma unroll
    for (int j = 0; j < 8; j++)
#pragma unroll
        for (int r = 0; r < 4; r++) acc_o[j][r] = 0.f;

    for (int kt = 0; kt < SDIM / 128; kt++) {
        const int kb0 = kt * 128;
        const int buf = kt & 1;
        __syncthreads();   // (A) prev chunk fully consumed (Vs, Ks[buf^1] free)

        // V(kt) -> Vs (waited just before PV)
#pragma unroll
        for (int i = 0; i < 8; i++) {
            const int r = ldr + i * 16;
            cp_async16(&Vs[r][ldc_], Vg + (size_t)(kb0 + r) * DH + ldc_);
        }
        CP_COMMIT();
        // K(kt+1) -> Ks[buf^1] (lands during this chunk's compute)
        if (kt < SDIM / 128 - 1) {
#pragma unroll
            for (int i = 0; i < 8; i++) {
                const int r = ldr + i * 16;
                cp_async16(&Ks[buf ^ 1][r][ldc_], Kg + (size_t)(kb0 + 128 + r) * DH + ldc_);
            }
            CP_COMMIT();
            CP_WAIT(2);    // K(kt) ready (V(kt), K(kt+1) still pending)
        } else {
            CP_WAIT(1);    // K(kt) ready (V(kt) pending)
        }
        // in-place RNA-tf32 of own K elements
#pragma unroll
        for (int i = 0; i < 8; i++) {
            const int r = ldr + i * 16;
            float4 x = *(float4*)&Ks[buf][r][ldc_];
            *(float4*)&Ks[buf][r][ldc_] = tf32x4(x);
        }
        __syncthreads();   // (B) Ks[buf] ready for all

        // ---- scores: 16 x 128 per warp ----
        float sacc[16][4];
#pragma unroll
        for (int j = 0; j < 16; j++)
#pragma unroll
            for (int r = 0; r < 4; r++) sacc[j][r] = 0.f;

#pragma unroll
        for (int ks = 0; ks < 8; ks++) {
            const int kb = ks * 8;
            unsigned a[4], b[16][2];
            a[0] = __float_as_uint(Qs[r0    ][kb + qd]);
            a[1] = __float_as_uint(Qs[r0 + 8][kb + qd]);
            a[2] = __float_as_uint(Qs[r0    ][kb + qd + 4]);
            a[3] = __float_as_uint(Qs[r0 + 8][kb + qd + 4]);
#pragma unroll
            for (int nt = 0; nt < 16; nt++) {
                const int c0 = nt * 8 + g;
                b[nt][0] = __float_as_uint(Ks[buf][c0][kb + qd]);
                b[nt][1] = __float_as_uint(Ks[buf][c0][kb + qd + 4]);
            }
#pragma unroll
            for (int nt = 0; nt < 16; nt++)
                mma_tf32(sacc[nt], a, b[nt]);
        }

        // ---- mask + scale + chunk max ----
        float cm_lo = -1e30f, cm_hi = -1e30f;
#pragma unroll
        for (int nt = 0; nt < 16; nt++) {
            const int c0 = kb0 + nt * 8 + 2 * qd;
            const bool z0 = (Ms[c0] == 0), z1 = (Ms[c0 + 1] == 0);
            float s0 = z0 ? -1e10f : sacc[nt][0] * 0.125f;
            float s1 = z1 ? -1e10f : sacc[nt][1] * 0.125f;
            float s2 = z0 ? -1e10f : sacc[nt][2] * 0.125f;
            float s3 = z1 ? -1e10f : sacc[nt][3] * 0.125f;
            sacc[nt][0] = s0; sacc[nt][1] = s1;
            sacc[nt][2] = s2; sacc[nt][3] = s3;
            cm_lo = fmaxf(cm_lo, fmaxf(s0, s1));
            cm_hi = fmaxf(cm_hi, fmaxf(s2, s3));
        }
#pragma unroll
        for (int o = 1; o <= 2; o <<= 1) {
            cm_lo = fmaxf(cm_lo, __shfl_xor_sync(0xffffffffu, cm_lo, o));
            cm_hi = fmaxf(cm_hi, __shfl_xor_sync(0xffffffffu, cm_hi, o));
        }

        const float mn_lo = fmaxf(m_lo, cm_lo), mn_hi = fmaxf(m_hi, cm_hi);
        const float rl = __expf(m_lo - mn_lo), rh = __expf(m_hi - mn_hi);

        // ---- exp, partial sums, stage P to smem (tf32) ----
        float ps_lo = 0.f, ps_hi = 0.f;
#pragma unroll
        for (int nt = 0; nt < 16; nt++) {
            const int c = nt * 8 + 2 * qd;
            const float p0 = __expf(sacc[nt][0] - mn_lo);
            const float p1 = __expf(sacc[nt][1] - mn_lo);
            const float p2 = __expf(sacc[nt][2] - mn_hi);
            const float p3 = __expf(sacc[nt][3] - mn_hi);
            ps_lo += p0 + p1; ps_hi += p2 + p3;
            *(float2*)&Ps[r0    ][c] = make_float2(to_tf32(p0), to_tf32(p1));
            *(float2*)&Ps[r0 + 8][c] = make_float2(to_tf32(p2), to_tf32(p3));
        }
#pragma unroll
        for (int o = 1; o <= 2; o <<= 1) {
            ps_lo += __shfl_xor_sync(0xffffffffu, ps_lo, o);
            ps_hi += __shfl_xor_sync(0xffffffffu, ps_hi, o);
        }
        s_lo = s_lo * rl + ps_lo;
        s_hi = s_hi * rh + ps_hi;
        m_lo = mn_lo; m_hi = mn_hi;

#pragma unroll
        for (int nt = 0; nt < 8; nt++) {
            acc_o[nt][0] *= rl; acc_o[nt][1] *= rl;
            acc_o[nt][2] *= rh; acc_o[nt][3] *= rh;
        }

        // ---- V arrival + in-place conversion ----
        if (kt < SDIM / 128 - 1) CP_WAIT(1); else CP_WAIT(0);
#pragma unroll
        for (int i = 0; i < 8; i++) {
            const int r = ldr + i * 16;
            float4 x = *(float4*)&Vs[r][ldc_];
            *(float4*)&Vs[r][ldc_] = tf32x4(x);
        }
        __syncthreads();   // (C) Vs ready; Ps visible (warp-local anyway)

        // ---- PV: O += P(16x128) @ V(128x64) ----
#pragma unroll
        for (int ks = 0; ks < 16; ks++) {
            const int kb = ks * 8;
            unsigned a[4], b[8][2];
            a[0] = __float_as_uint(Ps[r0    ][kb + qd]);
            a[1] = __float_as_uint(Ps[r0 + 8][kb + qd]);
            a[2] = __float_as_uint(Ps[r0    ][kb + qd + 4]);
            a[3] = __float_as_uint(Ps[r0 + 8][kb + qd + 4]);
#pragma unroll
            for (int nt = 0; nt < 8; nt++) {
                const int c0 = nt * 8 + g;
                b[nt][0] = __float_as_uint(Vs[kb + qd    ][c0]);
                b[nt][1] = __float_as_uint(Vs[kb + qd + 4][c0]);
            }
#pragma unroll
            for (int nt = 0; nt < 8; nt++)
                mma_tf32(acc_o[nt], a, b[nt]);
        }
    }

    // ---- epilogue: normalize, write ctx + stats ----
    const float inv_lo = 1.f / s_lo, inv_hi = 1.f / s_hi;
#pragma unroll
    for (int nt = 0; nt < 8; nt++) {
        const int d = h * DH + nt * 8 + 2 * qd;
        float2 v0, v1;
        v0.x = acc_o[nt][0] * inv_lo; v0.y = acc_o[nt][1] * inv_lo;
        v1.x = acc_o[nt][2] * inv_hi; v1.y = acc_o[nt][3] * inv_hi;
        *(float2*)&ctx[((size_t)(b_ * SDIM + q0 + r0    )) * HDIM + d] = v0;
        *(float2*)&ctx[((size_t)(b_ * SDIM + q0 + r0 + 8)) * HDIM + d] = v1;
    }
    if (qd == 0) {
        stats[(size_t)bh * SDIM + q0 + r0    ] = make_float2(m_lo, inv_lo);
        stats[(size_t)bh * SDIM + q0 + r0 + 8] = make_float2(m_hi, inv_hi);
    }
}

// ---------------------------------------------------------------------------
// Probs replay: recompute E tile (identical RNA-tf32 MMA), apply mask, then
// p = exp(s - m) * inv using flash stats; write probs (the 2nd output).
// Block tile 128x128, 2 CTAs/SM. 8 warps (4m x 2n), warp tile 32x64.
// ---------------------------------------------------------------------------
__global__ void __launch_bounds__(256, 2) probs_k64(
    const float* __restrict__ Qg, const float* __restrict__ Kg,
    float* __restrict__ att, const int* __restrict__ mask,
    const float2* __restrict__ stats)
{
    extern __shared__ char smem_raw[];
    float (*As)[68] = (float(*)[68])smem_raw;                       // 128 x 64
    float (*Bs)[68] = (float(*)[68])(smem_raw + 128 * 68 * 4);      // 128 x 64
    float* Sm = (float*)(smem_raw + 2 * 128 * 68 * 4);              // 128 row max
    float* Si = Sm + 128;                                           // 128 row inv
    int*   Mc = (int*)(Si + 128);                                   // 128 col mask

    const int bh = blockIdx.z;
    const float* A = Qg + (size_t)bh * SDIM * DH;
    const float* B = Kg + (size_t)bh * SDIM * DH;
    float* C = att + (size_t)bh * SDIM * SDIM;

    const int tid  = threadIdx.x;
    const int wid  = tid >> 5, lane = tid & 31;
    const int wm   = wid >> 1, wn = wid & 1;
    const int g    = lane >> 2, qd = lane & 3;
    const int brow = blockIdx.y * 128;
    const int bcol = blockIdx.x * 128;
    const int b_   = bh / NH;

#pragma unroll
    for (int i = 0; i < 8; i++) {
        const int idx = tid + i * 256;
        const int r = idx >> 4, c = (idx & 15) * 4;
        *(float4*)&As[r][c] = tf32x4(*(const float4*)(A + (size_t)(brow + r) * DH + c));
        *(float4*)&Bs[r][c] = tf32x4(*(const float4*)(B + (size_t)(bcol + r) * DH + c));
    }
    if (tid < 128) {
        const float2 st = stats[(size_t)bh * SDIM + brow + tid];
        Sm[tid] = st.x; Si[tid] = st.y;
    } else {
        Mc[tid - 128] = mask[b_ * SDIM + bcol + tid - 128];
    }
    __syncthreads();

    float acc[2][8][4];
#pragma unroll
    for (int i = 0; i < 2; i++)
#pragma unroll
        for (int j = 0; j < 8; j++)
#pragma unroll
            for (int r = 0; r < 4; r++) acc[i][j][r] = 0.f;

#pragma unroll
    for (int ks = 0; ks < 8; ks++) {
        const int kb = ks * 8;
        unsigned a[2][4], b[8][2];
#pragma unroll
        for (int mt = 0; mt < 2; mt++) {
            const int r0 = wm * 32 + mt * 16 + g;
            a[mt][0] = __float_as_uint(As[r0    ][kb + qd]);
            a[mt][1] = __float_as_uint(As[r0 + 8][kb + qd]);
            a[mt][2] = __float_as_uint(As[r0    ][kb + qd + 4]);
            a[mt][3] = __float_as_uint(As[r0 + 8][kb + qd + 4]);
        }
#pragma unroll
        for (int nt = 0; nt < 8; nt++) {
            const int c0 = wn * 64 + nt * 8 + g;
            b[nt][0] = __float_as_uint(Bs[c0][kb + qd]);
            b[nt][1] = __float_as_uint(Bs[c0][kb + qd + 4]);
        }
#pragma unroll
        for (int mt = 0; mt < 2; mt++)
#pragma unroll
            for (int nt = 0; nt < 8; nt++)
                mma_tf32(acc[mt][nt], a[mt], b[nt]);
    }

#pragma unroll
    for (int mt = 0; mt < 2; mt++) {
#pragma unroll
        for (int nt = 0; nt < 8; nt++) {
            const int lcc = wn * 64 + nt * 8 + 2 * qd;
            const bool z0 = (Mc[lcc] == 0), z1 = (Mc[lcc + 1] == 0);
#pragma unroll
            for (int half = 0; half < 2; half++) {
                const int lr = wm * 32 + mt * 16 + g + half * 8;
                const float m = Sm[lr], inv = Si[lr];
                float s0 = z0 ? -1e10f : acc[mt][nt][2 * half]     * 0.125f;
                float s1 = z1 ? -1e10f : acc[mt][nt][2 * half + 1] * 0.125f;
                float2 v;
                v.x = __expf(s0 - m) * inv;
                v.y = __expf(s1 - m) * inv;
                *(float2*)&C[(size_t)(brow + lr) * SDIM + bcol + lcc] = v;
            }
        }
    }
}

// ---------------------------------------------------------------------------
extern "C" void kernel_launch(void* const* d_in, const int* in_sizes, int n_in,
                              void* d_out, int out_size)
{
    const float* query  = (const float*)d_in[0];
    const float* key_in = (const float*)d_in[1];
    const float* value  = (const float*)d_in[2];
    const int*   mask   = (const int*)  d_in[3];
    const float* Wq = (const float*)d_in[4],  *bq = (const float*)d_in[5];
    const float* Wk = (const float*)d_in[6],  *bk = (const float*)d_in[7];
    const float* Wv = (const float*)d_in[8],  *bv = (const float*)d_in[9];
    const float* Wo = (const float*)d_in[10], *bo = (const float*)d_in[11];
    float* out = (float*)d_out;

    float *qbuf, *kbuf, *vbuf, *cbuf;
    float2* sbuf;
    cudaGetSymbolAddress((void**)&qbuf, g_Q);
    cudaGetSymbolAddress((void**)&kbuf, g_K);
    cudaGetSymbolAddress((void**)&vbuf, g_V);
    cudaGetSymbolAddress((void**)&cbuf, g_ctx);
    cudaGetSymbolAddress((void**)&sbuf, g_stats);

    const long long XE = (long long)BDIM * SDIM * HDIM;       // 8,388,608
    float* att = out + XE;                                    // [B,H,S,S]

    const int smem_f = 34816 + 69632 + 36864 + 67584 + 8192;  // 217,088
    const int smem_p = 2 * 128 * 68 * 4 + 2 * 128 * 4 + 128 * 4;  // 71,168
    cudaFuncSetAttribute(flash_attn, cudaFuncAttributeMaxDynamicSharedMemorySize, smem_f);
    cudaFuncSetAttribute(probs_k64, cudaFuncAttributeMaxDynamicSharedMemorySize, smem_p);

    // 1) QKV projections, scatter to [B,H,S,Dh]  (2 CTAs/SM)
    const dim3 gp(HDIM / 128, (BDIM * SDIM) / 128, 1);
    gemm128<1><<<gp, 256>>>(query,  Wq, bq, qbuf, HDIM, HDIM);
    gemm128<1><<<gp, 256>>>(key_in, Wk, bk, kbuf, HDIM, HDIM);
    gemm128<1><<<gp, 256>>>(value,  Wv, bv, vbuf, HDIM, HDIM);

    // 2) Flash attention -> ctx + stats (cp.async pipelined)
    flash_attn<<<dim3(SDIM / 128, BDIM * NH), 256, smem_f>>>(mask, cbuf, sbuf);

    // 3) Probs replay -> attention output (single store pass)
    probs_k64<<<dim3(SDIM / 128, SDIM / 128, BDIM * NH), 256, smem_p>>>(
        qbuf, kbuf, att, mask, sbuf);

    // 4) Output projection -> x
    gemm128<0><<<gp, 256>>>(cbuf, Wo, bo, out, HDIM, HDIM);
}

// round 12
// speedup vs baseline: 1.2283x; 1.2283x over previous
#include <cuda_runtime.h>
#include <cuda_fp16.h>
#include <cstdint>

#define BDIM 4
#define SDIM 2048
#define HDIM 1024
#define NH   16
#define DH   64

// Scratch (device globals: no allocation allowed in kernel_launch)
__device__ float g_Q[(size_t)BDIM * NH * SDIM * DH];
__device__ float g_K[(size_t)BDIM * NH * SDIM * DH];
__device__ float g_V[(size_t)BDIM * NH * SDIM * DH];
__device__ float g_ctx[(size_t)BDIM * SDIM * HDIM];
__device__ float2 g_stats[(size_t)BDIM * NH * SDIM];   // (row_max, 1/row_sum)

// ---------------------------------------------------------------------------
__device__ __forceinline__ float to_tf32(float x) {
    float r;
    asm("cvt.rna.tf32.f32 %0, %1;" : "=f"(r) : "f"(x));
    return r;
}
__device__ __forceinline__ float4 tf32x4(float4 v) {
    return make_float4(to_tf32(v.x), to_tf32(v.y), to_tf32(v.z), to_tf32(v.w));
}
__device__ __forceinline__ void mma_tf32(float* c, const unsigned* a,
                                         const unsigned* b) {
    asm volatile(
        "mma.sync.aligned.m16n8k8.row.col.f32.tf32.tf32.f32 "
        "{%0,%1,%2,%3}, {%4,%5,%6,%7}, {%8,%9}, {%0,%1,%2,%3};\n"
        : "+f"(c[0]), "+f"(c[1]), "+f"(c[2]), "+f"(c[3])
        : "r"(a[0]), "r"(a[1]), "r"(a[2]), "r"(a[3]), "r"(b[0]), "r"(b[1]));
}
__device__ __forceinline__ void mma_f16(float* c, const unsigned* a,
                                        const unsigned* b) {
    asm volatile(
        "mma.sync.aligned.m16n8k16.row.col.f32.f16.f16.f32 "
        "{%0,%1,%2,%3}, {%4,%5,%6,%7}, {%8,%9}, {%0,%1,%2,%3};\n"
        : "+f"(c[0]), "+f"(c[1]), "+f"(c[2]), "+f"(c[3])
        : "r"(a[0]), "r"(a[1]), "r"(a[2]), "r"(a[3]), "r"(b[0]), "r"(b[1]));
}
__device__ __forceinline__ uint2 f4_to_h4(float4 v) {
    __half2 lo = __floats2half2_rn(v.x, v.y);
    __half2 hi = __floats2half2_rn(v.z, v.w);
    uint2 r;
    r.x = *(unsigned*)&lo;
    r.y = *(unsigned*)&hi;
    return r;
}

// ---------------------------------------------------------------------------
// Dense GEMM (fp16 operands, fp32 accum): C = A[M,K] @ B[N,K]^T + bias.
// MODE 0: direct row-major C. MODE 1: scatter to [B,H,S,Dh].
// Block 128x128, BK=32, 256 threads, 8 warps (4m x 2n), warp tile 32x64.
// Double-buffered via register prefetch; ~120 regs, 40KB smem -> 2 CTAs/SM.
// ---------------------------------------------------------------------------
template <int MODE>
__global__ void __launch_bounds__(256, 2) gemm128h(
    const float* __restrict__ A, const float* __restrict__ Bm,
    const float* __restrict__ bias, float* __restrict__ C,
    int K, int ldc)
{
    __shared__ __half As[2][128][40];
    __shared__ __half Bs[2][128][40];

    const int tid  = threadIdx.x;
    const int wid  = tid >> 5, lane = tid & 31;
    const int wm   = wid >> 1, wn = wid & 1;
    const int g    = lane >> 2, qd = lane & 3;
    const int brow = blockIdx.y * 128;
    const int bcol = blockIdx.x * 128;

    const int lr = tid >> 1;          // 0..127
    const int lc = (tid & 1) * 16;    // 0 or 16

    float acc[2][8][4];
#pragma unroll
    for (int i = 0; i < 2; i++)
#pragma unroll
        for (int j = 0; j < 8; j++)
#pragma unroll
            for (int r = 0; r < 4; r++) acc[i][j][r] = 0.f;

    const float* Ap = A  + (size_t)(brow + lr) * K + lc;
    const float* Bp = Bm + (size_t)(bcol + lr) * K + lc;

    float4 pa[4], pb[4];
#pragma unroll
    for (int p = 0; p < 4; p++) {
        pa[p] = *(const float4*)(Ap + 4 * p);
        pb[p] = *(const float4*)(Bp + 4 * p);
    }
#pragma unroll
    for (int p = 0; p < 4; p++) {
        *(uint2*)&As[0][lr][lc + 4 * p] = f4_to_h4(pa[p]);
        *(uint2*)&Bs[0][lr][lc + 4 * p] = f4_to_h4(pb[p]);
    }
    __syncthreads();

    int buf = 0;
    for (int k0 = 0; k0 < K; k0 += 32, buf ^= 1) {
        const bool more = (k0 + 32) < K;
        if (more) {
#pragma unroll
            for (int p = 0; p < 4; p++) {
                pa[p] = *(const float4*)(Ap + k0 + 32 + 4 * p);
                pb[p] = *(const float4*)(Bp + k0 + 32 + 4 * p);
            }
        }

#pragma unroll
        for (int ks = 0; ks < 2; ks++) {
            const int kb = ks * 16;
            unsigned a[2][4], b[8][2];
#pragma unroll
            for (int mt = 0; mt < 2; mt++) {
                const int r0 = wm * 32 + mt * 16 + g;
                a[mt][0] = *(const unsigned*)&As[buf][r0    ][kb + 2 * qd];
                a[mt][1] = *(const unsigned*)&As[buf][r0 + 8][kb + 2 * qd];
                a[mt][2] = *(const unsigned*)&As[buf][r0    ][kb + 2 * qd + 8];
                a[mt][3] = *(const unsigned*)&As[buf][r0 + 8][kb + 2 * qd + 8];
            }
#pragma unroll
            for (int nt = 0; nt < 8; nt++) {
                const int c0 = wn * 64 + nt * 8 + g;
                b[nt][0] = *(const unsigned*)&Bs[buf][c0][kb + 2 * qd];
                b[nt][1] = *(const unsigned*)&Bs[buf][c0][kb + 2 * qd + 8];
            }
#pragma unroll
            for (int mt = 0; mt < 2; mt++)
#pragma unroll
                for (int nt = 0; nt < 8; nt++)
                    mma_f16(acc[mt][nt], a[mt], b[nt]);
        }

        if (more) {
#pragma unroll
            for (int p = 0; p < 4; p++) {
                *(uint2*)&As[buf ^ 1][lr][lc + 4 * p] = f4_to_h4(pa[p]);
                *(uint2*)&Bs[buf ^ 1][lr][lc + 4 * p] = f4_to_h4(pb[p]);
            }
            __syncthreads();
        }
    }

#pragma unroll
    for (int mt = 0; mt < 2; mt++) {
#pragma unroll
        for (int nt = 0; nt < 8; nt++) {
            const int cc = bcol + wn * 64 + nt * 8 + 2 * qd;
            const float bx = bias[cc], by = bias[cc + 1];
#pragma unroll
            for (int half = 0; half < 2; half++) {
                const int r = brow + wm * 32 + mt * 16 + g + half * 8;
                float2 v;
                v.x = acc[mt][nt][2 * half]     + bx;
                v.y = acc[mt][nt][2 * half + 1] + by;
                if (MODE == 1) {
                    const int b_ = r / SDIM, s = r % SDIM;
                    const int h  = cc / DH,  d = cc % DH;
                    *(float2*)&C[(((size_t)(b_ * NH + h)) * SDIM + s) * DH + d] = v;
                } else {
                    *(float2*)&C[(size_t)r * ldc + cc] = v;
                }
            }
        }
    }
}

// ---------------------------------------------------------------------------
// Flash attention (tf32, R10 version): per (b,h, 128 q-rows): stream K/V in
// 128-key chunks, online softmax, accumulate P@V in registers.
// Writes ctx + row stats ONLY. 8 warps m-stacked, warp = 16 q-rows.
// ---------------------------------------------------------------------------
__global__ void __launch_bounds__(256, 1) flash_attn(
    const int* __restrict__ mask, float* __restrict__ ctx,
    float2* __restrict__ stats)
{
    extern __shared__ char smem_raw[];
    float (*Qs)[68]  = (float(*)[68])smem_raw;                          // 128x64
    float (*Ks)[68]  = (float(*)[68])(smem_raw + 128 * 68 * 4);         // 128x64
    float (*Vs)[72]  = (float(*)[72])(smem_raw + 2 * 128 * 68 * 4);     // 128x64 [k][d]
    float (*Ps)[132] = (float(*)[132])(smem_raw + 2 * 128 * 68 * 4 + 128 * 72 * 4);
    int*   Ms        = (int*)(smem_raw + 2 * 128 * 68 * 4 + 128 * 72 * 4 + 128 * 132 * 4);

    const int bh = blockIdx.y;
    const int q0 = blockIdx.x * 128;
    const int b_ = bh / NH, h = bh % NH;
    const int tid = threadIdx.x, wid = tid >> 5, lane = tid & 31;
    const int g = lane >> 2, qd = lane & 3;
    const int r0 = wid * 16 + g;

    const float* Qg = g_Q + ((size_t)bh * SDIM + q0) * DH;
    const float* Kg = g_K + (size_t)bh * SDIM * DH;
    const float* Vg = g_V + (size_t)bh * SDIM * DH;

    // Load Q tile + mask row
#pragma unroll
    for (int i = 0; i < 8; i++) {
        const int idx = tid + i * 256;
        const int r = idx >> 4, c = (idx & 15) * 4;
        *(float4*)&Qs[r][c] = tf32x4(*(const float4*)(Qg + (size_t)r * DH + c));
    }
    for (int i = tid; i < SDIM / 4; i += 256)
        ((int4*)Ms)[i] = ((const int4*)(mask + b_ * SDIM))[i];

    float m_lo = -1e30f, m_hi = -1e30f, s_lo = 0.f, s_hi = 0.f;
    float acc_o[8][4];
#pragma unroll
    for (int j = 0; j < 8; j++)
#pragma unroll
        for (int r = 0; r < 4; r++) acc_o[j][r] = 0.f;

    for (int kt = 0; kt < SDIM / 128; kt++) {
        const int kb0 = kt * 128;
        __syncthreads();   // prev chunk consumed (and Q/mask ready on iter 0)
#pragma unroll
        for (int i = 0; i < 8; i++) {
            const int idx = tid + i * 256;
            const int r = idx >> 4, c = (idx & 15) * 4;
            *(float4*)&Ks[r][c] = tf32x4(*(const float4*)(Kg + (size_t)(kb0 + r) * DH + c));
            *(float4*)&Vs[r][c] = tf32x4(*(const float4*)(Vg + (size_t)(kb0 + r) * DH + c));
        }
        __syncthreads();

        // ---- scores: 16 x 128 per warp ----
        float sacc[16][4];
#pragma unroll
        for (int j = 0; j < 16; j++)
#pragma unroll
            for (int r = 0; r < 4; r++) sacc[j][r] = 0.f;

#pragma unroll
        for (int ks = 0; ks < 8; ks++) {
            const int kb = ks * 8;
            unsigned a[4], b[16][2];
            a[0] = __float_as_uint(Qs[r0    ][kb + qd]);
            a[1] = __float_as_uint(Qs[r0 + 8][kb + qd]);
            a[2] = __float_as_uint(Qs[r0    ][kb + qd + 4]);
            a[3] = __float_as_uint(Qs[r0 + 8][kb + qd + 4]);
#pragma unroll
            for (int nt = 0; nt < 16; nt++) {
                const int c0 = nt * 8 + g;
                b[nt][0] = __float_as_uint(Ks[c0][kb + qd]);
                b[nt][1] = __float_as_uint(Ks[c0][kb + qd + 4]);
            }
#pragma unroll
            for (int nt = 0; nt < 16; nt++)
                mma_tf32(sacc[nt], a, b[nt]);
        }

        // ---- mask + scale + chunk max ----
        float cm_lo = -1e30f, cm_hi = -1e30f;
#pragma unroll
        for (int nt = 0; nt < 16; nt++) {
            const int c0 = kb0 + nt * 8 + 2 * qd;
            const bool z0 = (Ms[c0] == 0), z1 = (Ms[c0 + 1] == 0);
            float s0 = z0 ? -1e10f : sacc[nt][0] * 0.125f;
            float s1 = z1 ? -1e10f : sacc[nt][1] * 0.125f;
            float s2 = z0 ? -1e10f : sacc[nt][2] * 0.125f;
            float s3 = z1 ? -1e10f : sacc[nt][3] * 0.125f;
            sacc[nt][0] = s0; sacc[nt][1] = s1;
            sacc[nt][2] = s2; sacc[nt][3] = s3;
            cm_lo = fmaxf(cm_lo, fmaxf(s0, s1));
            cm_hi = fmaxf(cm_hi, fmaxf(s2, s3));
        }
#pragma unroll
        for (int o = 1; o <= 2; o <<= 1) {
            cm_lo = fmaxf(cm_lo, __shfl_xor_sync(0xffffffffu, cm_lo, o));
            cm_hi = fmaxf(cm_hi, __shfl_xor_sync(0xffffffffu, cm_hi, o));
        }

        const float mn_lo = fmaxf(m_lo, cm_lo), mn_hi = fmaxf(m_hi, cm_hi);
        const float rl = __expf(m_lo - mn_lo), rh = __expf(m_hi - mn_hi);

        // ---- exp, partial sums, stage P to smem (tf32) ----
        float ps_lo = 0.f, ps_hi = 0.f;
#pragma unroll
        for (int nt = 0; nt < 16; nt++) {
            const int c = nt * 8 + 2 * qd;
            const float p0 = __expf(sacc[nt][0] - mn_lo);
            const float p1 = __expf(sacc[nt][1] - mn_lo);
            const float p2 = __expf(sacc[nt][2] - mn_hi);
            const float p3 = __expf(sacc[nt][3] - mn_hi);
            ps_lo += p0 + p1; ps_hi += p2 + p3;
            *(float2*)&Ps[r0    ][c] = make_float2(to_tf32(p0), to_tf32(p1));
            *(float2*)&Ps[r0 + 8][c] = make_float2(to_tf32(p2), to_tf32(p3));
        }
#pragma unroll
        for (int o = 1; o <= 2; o <<= 1) {
            ps_lo += __shfl_xor_sync(0xffffffffu, ps_lo, o);
            ps_hi += __shfl_xor_sync(0xffffffffu, ps_hi, o);
        }
        s_lo = s_lo * rl + ps_lo;
        s_hi = s_hi * rh + ps_hi;
        m_lo = mn_lo; m_hi = mn_hi;

        // rescale O accumulators
#pragma unroll
        for (int nt = 0; nt < 8; nt++) {
            acc_o[nt][0] *= rl; acc_o[nt][1] *= rl;
            acc_o[nt][2] *= rh; acc_o[nt][3] *= rh;
        }
        __syncwarp();

        // ---- PV: O += P(16x128) @ V(128x64) ----
#pragma unroll
        for (int ks = 0; ks < 16; ks++) {
            const int kb = ks * 8;
            unsigned a[4], b[8][2];
            a[0] = __float_as_uint(Ps[r0    ][kb + qd]);
            a[1] = __float_as_uint(Ps[r0 + 8][kb + qd]);
            a[2] = __float_as_uint(Ps[r0    ][kb + qd + 4]);
            a[3] = __float_as_uint(Ps[r0 + 8][kb + qd + 4]);
#pragma unroll
            for (int nt = 0; nt < 8; nt++) {
                const int c0 = nt * 8 + g;
                b[nt][0] = __float_as_uint(Vs[kb + qd    ][c0]);
                b[nt][1] = __float_as_uint(Vs[kb + qd + 4][c0]);
            }
#pragma unroll
            for (int nt = 0; nt < 8; nt++)
                mma_tf32(acc_o[nt], a, b[nt]);
        }
    }

    // ---- epilogue: normalize, write ctx + stats ----
    const float inv_lo = 1.f / s_lo, inv_hi = 1.f / s_hi;
#pragma unroll
    for (int nt = 0; nt < 8; nt++) {
        const int d = h * DH + nt * 8 + 2 * qd;
        float2 v0, v1;
        v0.x = acc_o[nt][0] * inv_lo; v0.y = acc_o[nt][1] * inv_lo;
        v1.x = acc_o[nt][2] * inv_hi; v1.y = acc_o[nt][3] * inv_hi;
        *(float2*)&ctx[((size_t)(b_ * SDIM + q0 + r0    )) * HDIM + d] = v0;
        *(float2*)&ctx[((size_t)(b_ * SDIM + q0 + r0 + 8)) * HDIM + d] = v1;
    }
    if (qd == 0) {
        stats[(size_t)bh * SDIM + q0 + r0    ] = make_float2(m_lo, inv_lo);
        stats[(size_t)bh * SDIM + q0 + r0 + 8] = make_float2(m_hi, inv_hi);
    }
}

// ---------------------------------------------------------------------------
// Probs replay (tf32, identical MMA sequence to flash): recompute E tile,
// apply mask, p = exp(s - m) * inv with flash stats; write probs output.
// Block tile 128x128, 2 CTAs/SM. 8 warps (4m x 2n), warp tile 32x64.
// ---------------------------------------------------------------------------
__global__ void __launch_bounds__(256, 2) probs_k64(
    const float* __restrict__ Qg, const float* __restrict__ Kg,
    float* __restrict__ att, const int* __restrict__ mask,
    const float2* __restrict__ stats)
{
    extern __shared__ char smem_raw[];
    float (*As)[68] = (float(*)[68])smem_raw;                       // 128 x 64
    float (*Bs)[68] = (float(*)[68])(smem_raw + 128 * 68 * 4);      // 128 x 64
    float* Sm = (float*)(smem_raw + 2 * 128 * 68 * 4);              // 128 row max
    float* Si = Sm + 128;                                           // 128 row inv
    int*   Mc = (int*)(Si + 128);                                   // 128 col mask

    const int bh = blockIdx.z;
    const float* A = Qg + (size_t)bh * SDIM * DH;
    const float* B = Kg + (size_t)bh * SDIM * DH;
    float* C = att + (size_t)bh * SDIM * SDIM;

    const int tid  = threadIdx.x;
    const int wid  = tid >> 5, lane = tid & 31;
    const int wm   = wid >> 1, wn = wid & 1;
    const int g    = lane >> 2, qd = lane & 3;
    const int brow = blockIdx.y * 128;
    const int bcol = blockIdx.x * 128;
    const int b_   = bh / NH;

#pragma unroll
    for (int i = 0; i < 8; i++) {
        const int idx = tid + i * 256;
        const int r = idx >> 4, c = (idx & 15) * 4;
        *(float4*)&As[r][c] = tf32x4(*(const float4*)(A + (size_t)(brow + r) * DH + c));
        *(float4*)&Bs[r][c] = tf32x4(*(const float4*)(B + (size_t)(bcol + r) * DH + c));
    }
    if (tid < 128) {
        const float2 st = stats[(size_t)bh * SDIM + brow + tid];
        Sm[tid] = st.x; Si[tid] = st.y;
    } else {
        Mc[tid - 128] = mask[b_ * SDIM + bcol + tid - 128];
    }
    __syncthreads();

    float acc[2][8][4];
#pragma unroll
    for (int i = 0; i < 2; i++)
#pragma unroll
        for (int j = 0; j < 8; j++)
#pragma unroll
            for (int r = 0; r < 4; r++) acc[i][j][r] = 0.f;

#pragma unroll
    for (int ks = 0; ks < 8; ks++) {
        const int kb = ks * 8;
        unsigned a[2][4], b[8][2];
#pragma unroll
        for (int mt = 0; mt < 2; mt++) {
            const int r0 = wm * 32 + mt * 16 + g;
            a[mt][0] = __float_as_uint(As[r0    ][kb + qd]);
            a[mt][1] = __float_as_uint(As[r0 + 8][kb + qd]);
            a[mt][2] = __float_as_uint(As[r0    ][kb + qd + 4]);
            a[mt][3] = __float_as_uint(As[r0 + 8][kb + qd + 4]);
        }
#pragma unroll
        for (int nt = 0; nt < 8; nt++) {
            const int c0 = wn * 64 + nt * 8 + g;
            b[nt][0] = __float_as_uint(Bs[c0][kb + qd]);
            b[nt][1] = __float_as_uint(Bs[c0][kb + qd + 4]);
        }
#pragma unroll
        for (int mt = 0; mt < 2; mt++)
#pragma unroll
            for (int nt = 0; nt < 8; nt++)
                mma_tf32(acc[mt][nt], a[mt], b[nt]);
    }

#pragma unroll
    for (int mt = 0; mt < 2; mt++) {
#pragma unroll
        for (int nt = 0; nt < 8; nt++) {
            const int lcc = wn * 64 + nt * 8 + 2 * qd;
            const bool z0 = (Mc[lcc] == 0), z1 = (Mc[lcc + 1] == 0);
#pragma unroll
            for (int half = 0; half < 2; half++) {
                const int lr = wm * 32 + mt * 16 + g + half * 8;
                const float m = Sm[lr], inv = Si[lr];
                float s0 = z0 ? -1e10f : acc[mt][nt][2 * half]     * 0.125f;
                float s1 = z1 ? -1e10f : acc[mt][nt][2 * half + 1] * 0.125f;
                float2 v;
                v.x = __expf(s0 - m) * inv;
                v.y = __expf(s1 - m) * inv;
                *(float2*)&C[(size_t)(brow + lr) * SDIM + bcol + lcc] = v;
            }
        }
    }
}

// ---------------------------------------------------------------------------
extern "C" void kernel_launch(void* const* d_in, const int* in_sizes, int n_in,
                              void* d_out, int out_size)
{
    const float* query  = (const float*)d_in[0];
    const float* key_in = (const float*)d_in[1];
    const float* value  = (const float*)d_in[2];
    const int*   mask   = (const int*)  d_in[3];
    const float* Wq = (const float*)d_in[4],  *bq = (const float*)d_in[5];
    const float* Wk = (const float*)d_in[6],  *bk = (const float*)d_in[7];
    const float* Wv = (const float*)d_in[8],  *bv = (const float*)d_in[9];
    const float* Wo = (const float*)d_in[10], *bo = (const float*)d_in[11];
    float* out = (float*)d_out;

    float *qbuf, *kbuf, *vbuf, *cbuf;
    float2* sbuf;
    cudaGetSymbolAddress((void**)&qbuf, g_Q);
    cudaGetSymbolAddress((void**)&kbuf, g_K);
    cudaGetSymbolAddress((void**)&vbuf, g_V);
    cudaGetSymbolAddress((void**)&cbuf, g_ctx);
    cudaGetSymbolAddress((void**)&sbuf, g_stats);

    const long long XE = (long long)BDIM * SDIM * HDIM;       // 8,388,608
    float* att = out + XE;                                    // [B,H,S,S]

    const int smem_f = 2 * 128 * 68 * 4 + 128 * 72 * 4 + 128 * 132 * 4
                     + SDIM * 4;                                        // 182,272
    const int smem_p = 2 * 128 * 68 * 4 + 2 * 128 * 4 + 128 * 4;        // 71,168
    cudaFuncSetAttribute(flash_attn, cudaFuncAttributeMaxDynamicSharedMemorySize, smem_f);
    cudaFuncSetAttribute(probs_k64, cudaFuncAttributeMaxDynamicSharedMemorySize, smem_p);

    // 1) QKV projections (fp16 MMA), scatter to [B,H,S,Dh]
    const dim3 gp(HDIM / 128, (BDIM * SDIM) / 128, 1);
    gemm128h<1><<<gp, 256>>>(query,  Wq, bq, qbuf, HDIM, HDIM);
    gemm128h<1><<<gp, 256>>>(key_in, Wk, bk, kbuf, HDIM, HDIM);
    gemm128h<1><<<gp, 256>>>(value,  Wv, bv, vbuf, HDIM, HDIM);

    // 2) Flash attention (tf32) -> ctx + stats
    flash_attn<<<dim3(SDIM / 128, BDIM * NH), 256, smem_f>>>(mask, cbuf, sbuf);

    // 3) Probs replay (tf32, consistent with flash) -> attention output
    probs_k64<<<dim3(SDIM / 128, SDIM / 128, BDIM * NH), 256, smem_p>>>(
        qbuf, kbuf, att, mask, sbuf);

    // 4) Output projection (fp16 MMA) -> x
    gemm128h<0><<<gp, 256>>>(cbuf, Wo, bo, out, HDIM, HDIM);
}

// round 14
// speedup vs baseline: 1.4587x; 1.1876x over previous
#include <cuda_runtime.h>
#include <cuda_fp16.h>
#include <cstdint>

#define BDIM 4
#define SDIM 2048
#define HDIM 1024
#define NH   16
#define DH   64

// Scratch (device globals: no allocation allowed in kernel_launch)
__device__ float g_Q[(size_t)BDIM * NH * SDIM * DH];
__device__ float g_K[(size_t)BDIM * NH * SDIM * DH];
__device__ float g_V[(size_t)BDIM * NH * SDIM * DH];
__device__ float g_ctx[(size_t)BDIM * SDIM * HDIM];
__device__ float2 g_stats[(size_t)BDIM * NH * SDIM];   // (row_max, 1/row_sum)

// ---------------------------------------------------------------------------
__device__ __forceinline__ void mma_f16(float* c, const unsigned* a,
                                        const unsigned* b) {
    asm volatile(
        "mma.sync.aligned.m16n8k16.row.col.f32.f16.f16.f32 "
        "{%0,%1,%2,%3}, {%4,%5,%6,%7}, {%8,%9}, {%0,%1,%2,%3};\n"
        : "+f"(c[0]), "+f"(c[1]), "+f"(c[2]), "+f"(c[3])
        : "r"(a[0]), "r"(a[1]), "r"(a[2]), "r"(a[3]), "r"(b[0]), "r"(b[1]));
}
__device__ __forceinline__ uint2 f4_to_h4(float4 v) {
    __half2 lo = __floats2half2_rn(v.x, v.y);
    __half2 hi = __floats2half2_rn(v.z, v.w);
    uint2 r;
    r.x = *(unsigned*)&lo;
    r.y = *(unsigned*)&hi;
    return r;
}

// ---------------------------------------------------------------------------
// Dense GEMM (fp16 operands, fp32 accum): C = A[M,K] @ B[N,K]^T + bias.
// MODE 0: direct row-major C. MODE 1: scatter to [B,H,S,Dh].
// Block 128x128, BK=32, 256 threads, 8 warps (4m x 2n), warp tile 32x64.
// ---------------------------------------------------------------------------
template <int MODE>
__global__ void __launch_bounds__(256, 2) gemm128h(
    const float* __restrict__ A, const float* __restrict__ Bm,
    const float* __restrict__ bias, float* __restrict__ C,
    int K, int ldc)
{
    __shared__ __half As[2][128][40];
    __shared__ __half Bs[2][128][40];

    const int tid  = threadIdx.x;
    const int wid  = tid >> 5, lane = tid & 31;
    const int wm   = wid >> 1, wn = wid & 1;
    const int g    = lane >> 2, qd = lane & 3;
    const int brow = blockIdx.y * 128;
    const int bcol = blockIdx.x * 128;

    const int lr = tid >> 1;          // 0..127
    const int lc = (tid & 1) * 16;    // 0 or 16

    float acc[2][8][4];
#pragma unroll
    for (int i = 0; i < 2; i++)
#pragma unroll
        for (int j = 0; j < 8; j++)
#pragma unroll
            for (int r = 0; r < 4; r++) acc[i][j][r] = 0.f;

    const float* Ap = A  + (size_t)(brow + lr) * K + lc;
    const float* Bp = Bm + (size_t)(bcol + lr) * K + lc;

    float4 pa[4], pb[4];
#pragma unroll
    for (int p = 0; p < 4; p++) {
        pa[p] = *(const float4*)(Ap + 4 * p);
        pb[p] = *(const float4*)(Bp + 4 * p);
    }
#pragma unroll
    for (int p = 0; p < 4; p++) {
        *(uint2*)&As[0][lr][lc + 4 * p] = f4_to_h4(pa[p]);
        *(uint2*)&Bs[0][lr][lc + 4 * p] = f4_to_h4(pb[p]);
    }
    __syncthreads();

    int buf = 0;
    for (int k0 = 0; k0 < K; k0 += 32, buf ^= 1) {
        const bool more = (k0 + 32) < K;
        if (more) {
#pragma unroll
            for (int p = 0; p < 4; p++) {
                pa[p] = *(const float4*)(Ap + k0 + 32 + 4 * p);
                pb[p] = *(const float4*)(Bp + k0 + 32 + 4 * p);
            }
        }

#pragma unroll
        for (int ks = 0; ks < 2; ks++) {
            const int kb = ks * 16;
            unsigned a[2][4], b[8][2];
#pragma unroll
            for (int mt = 0; mt < 2; mt++) {
                const int r0 = wm * 32 + mt * 16 + g;
                a[mt][0] = *(const unsigned*)&As[buf][r0    ][kb + 2 * qd];
                a[mt][1] = *(const unsigned*)&As[buf][r0 + 8][kb + 2 * qd];
                a[mt][2] = *(const unsigned*)&As[buf][r0    ][kb + 2 * qd + 8];
                a[mt][3] = *(const unsigned*)&As[buf][r0 + 8][kb + 2 * qd + 8];
            }
#pragma unroll
            for (int nt = 0; nt < 8; nt++) {
                const int c0 = wn * 64 + nt * 8 + g;
                b[nt][0] = *(const unsigned*)&Bs[buf][c0][kb + 2 * qd];
                b[nt][1] = *(const unsigned*)&Bs[buf][c0][kb + 2 * qd + 8];
            }
#pragma unroll
            for (int mt = 0; mt < 2; mt++)
#pragma unroll
                for (int nt = 0; nt < 8; nt++)
                    mma_f16(acc[mt][nt], a[mt], b[nt]);
        }

        if (more) {
#pragma unroll
            for (int p = 0; p < 4; p++) {
                *(uint2*)&As[buf ^ 1][lr][lc + 4 * p] = f4_to_h4(pa[p]);
                *(uint2*)&Bs[buf ^ 1][lr][lc + 4 * p] = f4_to_h4(pb[p]);
            }
            __syncthreads();
        }
    }

#pragma unroll
    for (int mt = 0; mt < 2; mt++) {
#pragma unroll
        for (int nt = 0; nt < 8; nt++) {
            const int cc = bcol + wn * 64 + nt * 8 + 2 * qd;
            const float bx = bias[cc], by = bias[cc + 1];
#pragma unroll
            for (int half = 0; half < 2; half++) {
                const int r = brow + wm * 32 + mt * 16 + g + half * 8;
                float2 v;
                v.x = acc[mt][nt][2 * half]     + bx;
                v.y = acc[mt][nt][2 * half + 1] + by;
                if (MODE == 1) {
                    const int b_ = r / SDIM, s = r % SDIM;
                    const int h  = cc / DH,  d = cc % DH;
                    *(float2*)&C[(((size_t)(b_ * NH + h)) * SDIM + s) * DH + d] = v;
                } else {
                    *(float2*)&C[(size_t)r * ldc + cc] = v;
                }
            }
        }
    }
}

// ---------------------------------------------------------------------------
// Flash attention, fp16 MMA core: per (b,h, 128 q-rows): stream K/V in
// 128-key chunks, online softmax (fp32 stats), P@V accumulate (fp32 acc).
// Scores use m16n8k16 fp16 with __floats2half2_rn operands -- the probs
// replay kernel uses the IDENTICAL sequence, so stats are consistent.
// ---------------------------------------------------------------------------
__global__ void __launch_bounds__(256, 1) flash_attn(
    const int* __restrict__ mask, float* __restrict__ ctx,
    float2* __restrict__ stats)
{
    extern __shared__ char smem_raw[];
    __half (*Qs)[72]  = (__half(*)[72])smem_raw;                    // 128 x 64
    __half (*Ks)[72]  = (__half(*)[72])(smem_raw + 18432);          // 128 x 64
    __half (*Vs)[136] = (__half(*)[136])(smem_raw + 36864);         // 64(d) x 128(k)
    __half (*Ps)[136] = (__half(*)[136])(smem_raw + 54272);         // 128 x 128
    int*    Ms        = (int*)(smem_raw + 89088);                   // 2048

    const int bh = blockIdx.y;
    const int q0 = blockIdx.x * 128;
    const int b_ = bh / NH, h = bh % NH;
    const int tid = threadIdx.x, wid = tid >> 5, lane = tid & 31;
    const int g = lane >> 2, qd = lane & 3;
    const int r0 = wid * 16 + g;

    const float* Qg = g_Q + ((size_t)bh * SDIM + q0) * DH;
    const float* Kg = g_K + (size_t)bh * SDIM * DH;
    const float* Vg = g_V + (size_t)bh * SDIM * DH;

    // Stage Q (fp16) + mask
#pragma unroll
    for (int i = 0; i < 8; i++) {
        const int idx = tid + i * 256;
        const int r = idx >> 4, c = (idx & 15) * 4;
        *(uint2*)&Qs[r][c] = f4_to_h4(*(const float4*)(Qg + (size_t)r * DH + c));
    }
    for (int i = tid; i < SDIM / 4; i += 256)
        ((int4*)Ms)[i] = ((const int4*)(mask + b_ * SDIM))[i];

    float m_lo = -1e30f, m_hi = -1e30f, s_lo = 0.f, s_hi = 0.f;
    float acc_o[8][4];
#pragma unroll
    for (int j = 0; j < 8; j++)
#pragma unroll
        for (int r = 0; r < 4; r++) acc_o[j][r] = 0.f;

    const int r2 = tid >> 4;            // 0..15
    const int vc = (tid & 15) * 4;      // 0..60

    for (int kt = 0; kt < SDIM / 128; kt++) {
        const int kb0 = kt * 128;
        __syncthreads();   // prev chunk consumed (and Q/mask ready on iter 0)

        // K chunk -> Ks [k][d] fp16
#pragma unroll
        for (int i = 0; i < 8; i++) {
            const int idx = tid + i * 256;
            const int r = idx >> 4, c = (idx & 15) * 4;
            *(uint2*)&Ks[r][c] = f4_to_h4(*(const float4*)(Kg + (size_t)(kb0 + r) * DH + c));
        }
        // V chunk -> Vs TRANSPOSED [d][k] fp16 (half2 per k-pair)
#pragma unroll
        for (int i = 0; i < 4; i++) {
            const int k0 = 2 * (r2 + i * 16);
            float4 f0 = *(const float4*)(Vg + (size_t)(kb0 + k0    ) * DH + vc);
            float4 f1 = *(const float4*)(Vg + (size_t)(kb0 + k0 + 1) * DH + vc);
            *(__half2*)&Vs[vc + 0][k0] = __floats2half2_rn(f0.x, f1.x);
            *(__half2*)&Vs[vc + 1][k0] = __floats2half2_rn(f0.y, f1.y);
            *(__half2*)&Vs[vc + 2][k0] = __floats2half2_rn(f0.z, f1.z);
            *(__half2*)&Vs[vc + 3][k0] = __floats2half2_rn(f0.w, f1.w);
        }
        __syncthreads();

        // ---- scores: 16 x 128 per warp, fp16 k16 x 4 steps ----
        float sacc[16][4];
#pragma unroll
        for (int j = 0; j < 16; j++)
#pragma unroll
            for (int r = 0; r < 4; r++) sacc[j][r] = 0.f;

#pragma unroll
        for (int ks = 0; ks < 4; ks++) {
            const int kb = ks * 16;
            unsigned a[4], b[16][2];
            a[0] = *(const unsigned*)&Qs[r0    ][kb + 2 * qd];
            a[1] = *(const unsigned*)&Qs[r0 + 8][kb + 2 * qd];
            a[2] = *(const unsigned*)&Qs[r0    ][kb + 2 * qd + 8];
            a[3] = *(const unsigned*)&Qs[r0 + 8][kb + 2 * qd + 8];
#pragma unroll
            for (int nt = 0; nt < 16; nt++) {
                const int c0 = nt * 8 + g;
                b[nt][0] = *(const unsigned*)&Ks[c0][kb + 2 * qd];
                b[nt][1] = *(const unsigned*)&Ks[c0][kb + 2 * qd + 8];
            }
#pragma unroll
            for (int nt = 0; nt < 16; nt++)
                mma_f16(sacc[nt], a, b[nt]);
        }

        // ---- mask + scale + chunk max ----
        float cm_lo = -1e30f, cm_hi = -1e30f;
#pragma unroll
        for (int nt = 0; nt < 16; nt++) {
            const int c0 = kb0 + nt * 8 + 2 * qd;
            const bool z0 = (Ms[c0] == 0), z1 = (Ms[c0 + 1] == 0);
            float s0 = z0 ? -1e10f : sacc[nt][0] * 0.125f;
            float s1 = z1 ? -1e10f : sacc[nt][1] * 0.125f;
            float s2 = z0 ? -1e10f : sacc[nt][2] * 0.125f;
            float s3 = z1 ? -1e10f : sacc[nt][3] * 0.125f;
            sacc[nt][0] = s0; sacc[nt][1] = s1;
            sacc[nt][2] = s2; sacc[nt][3] = s3;
            cm_lo = fmaxf(cm_lo, fmaxf(s0, s1));
            cm_hi = fmaxf(cm_hi, fmaxf(s2, s3));
        }
#pragma unroll
        for (int o = 1; o <= 2; o <<= 1) {
            cm_lo = fmaxf(cm_lo, __shfl_xor_sync(0xffffffffu, cm_lo, o));
            cm_hi = fmaxf(cm_hi, __shfl_xor_sync(0xffffffffu, cm_hi, o));
        }

        const float mn_lo = fmaxf(m_lo, cm_lo), mn_hi = fmaxf(m_hi, cm_hi);
        const float rl = __expf(m_lo - mn_lo), rh = __expf(m_hi - mn_hi);

        // ---- exp (fp32 sums), stage P to smem as fp16 ----
        float ps_lo = 0.f, ps_hi = 0.f;
#pragma unroll
        for (int nt = 0; nt < 16; nt++) {
            const int c = nt * 8 + 2 * qd;
            const float p0 = __expf(sacc[nt][0] - mn_lo);
            const float p1 = __expf(sacc[nt][1] - mn_lo);
            const float p2 = __expf(sacc[nt][2] - mn_hi);
            const float p3 = __expf(sacc[nt][3] - mn_hi);
            ps_lo += p0 + p1; ps_hi += p2 + p3;
            *(__half2*)&Ps[r0    ][c] = __floats2half2_rn(p0, p1);
            *(__half2*)&Ps[r0 + 8][c] = __floats2half2_rn(p2, p3);
        }
#pragma unroll
        for (int o = 1; o <= 2; o <<= 1) {
            ps_lo += __shfl_xor_sync(0xffffffffu, ps_lo, o);
            ps_hi += __shfl_xor_sync(0xffffffffu, ps_hi, o);
        }
        s_lo = s_lo * rl + ps_lo;
        s_hi = s_hi * rh + ps_hi;
        m_lo = mn_lo; m_hi = mn_hi;

        // rescale O accumulators
#pragma unroll
        for (int nt = 0; nt < 8; nt++) {
            acc_o[nt][0] *= rl; acc_o[nt][1] *= rl;
            acc_o[nt][2] *= rh; acc_o[nt][3] *= rh;
        }
        __syncwarp();

        // ---- PV: O += P(16x128) @ V(128x64), fp16 k16 x 8 steps ----
#pragma unroll
        for (int ks = 0; ks < 8; ks++) {
            const int kb = ks * 16;
            unsigned a[4], b[8][2];
            a[0] = *(const unsigned*)&Ps[r0    ][kb + 2 * qd];
            a[1] = *(const unsigned*)&Ps[r0 + 8][kb + 2 * qd];
            a[2] = *(const unsigned*)&Ps[r0    ][kb + 2 * qd + 8];
            a[3] = *(const unsigned*)&Ps[r0 + 8][kb + 2 * qd + 8];
#pragma unroll
            for (int nt = 0; nt < 8; nt++) {
                const int c0 = nt * 8 + g;
                b[nt][0] = *(const unsigned*)&Vs[c0][kb + 2 * qd];
                b[nt][1] = *(const unsigned*)&Vs[c0][kb + 2 * qd + 8];
            }
#pragma unroll
            for (int nt = 0; nt < 8; nt++)
                mma_f16(acc_o[nt], a, b[nt]);
        }
    }

    // ---- epilogue: normalize, write ctx + stats ----
    const float inv_lo = 1.f / s_lo, inv_hi = 1.f / s_hi;
#pragma unroll
    for (int nt = 0; nt < 8; nt++) {
        const int d = h * DH + nt * 8 + 2 * qd;
        float2 v0, v1;
        v0.x = acc_o[nt][0] * inv_lo; v0.y = acc_o[nt][1] * inv_lo;
        v1.x = acc_o[nt][2] * inv_hi; v1.y = acc_o[nt][3] * inv_hi;
        *(float2*)&ctx[((size_t)(b_ * SDIM + q0 + r0    )) * HDIM + d] = v0;
        *(float2*)&ctx[((size_t)(b_ * SDIM + q0 + r0 + 8)) * HDIM + d] = v1;
    }
    if (qd == 0) {
        stats[(size_t)bh * SDIM + q0 + r0    ] = make_float2(m_lo, inv_lo);
        stats[(size_t)bh * SDIM + q0 + r0 + 8] = make_float2(m_hi, inv_hi);
    }
}

// ---------------------------------------------------------------------------
// Probs replay (fp16 MMA, IDENTICAL sequence to flash scores): recompute
// E tile, mask, p = exp(s - m) * inv with flash stats; write probs output.
// Block tile 128x128, 2 CTAs/SM. 8 warps (4m x 2n), warp tile 32x64.
// ---------------------------------------------------------------------------
__global__ void __launch_bounds__(256, 2) probs_k64(
    const float* __restrict__ Qg, const float* __restrict__ Kg,
    float* __restrict__ att, const int* __restrict__ mask,
    const float2* __restrict__ stats)
{
    extern __shared__ char smem_raw[];
    __half (*As)[72] = (__half(*)[72])smem_raw;                     // 128 x 64
    __half (*Bs)[72] = (__half(*)[72])(smem_raw + 18432);           // 128 x 64
    float* Sm = (float*)(smem_raw + 36864);                         // 128 row max
    float* Si = Sm + 128;                                           // 128 row inv
    int*   Mc = (int*)(Si + 128);                                   // 128 col mask

    const int bh = blockIdx.z;
    const float* A = Qg + (size_t)bh * SDIM * DH;
    const float* B = Kg + (size_t)bh * SDIM * DH;
    float* C = att + (size_t)bh * SDIM * SDIM;

    const int tid  = threadIdx.x;
    const int wid  = tid >> 5, lane = tid & 31;
    const int wm   = wid >> 1, wn = wid & 1;
    const int g    = lane >> 2, qd = lane & 3;
    const int brow = blockIdx.y * 128;
    const int bcol = blockIdx.x * 128;
    const int b_   = bh / NH;

#pragma unroll
    for (int i = 0; i < 8; i++) {
        const int idx = tid + i * 256;
        const int r = idx >> 4, c = (idx & 15) * 4;
        *(uint2*)&As[r][c] = f4_to_h4(*(const float4*)(A + (size_t)(brow + r) * DH + c));
        *(uint2*)&Bs[r][c] = f4_to_h4(*(const float4*)(B + (size_t)(bcol + r) * DH + c));
    }
    if (tid < 128) {
        const float2 st = stats[(size_t)bh * SDIM + brow + tid];
        Sm[tid] = st.x; Si[tid] = st.y;
    } else {
        Mc[tid - 128] = mask[b_ * SDIM + bcol + tid - 128];
    }
    __syncthreads();

    float acc[2][8][4];
#pragma unroll
    for (int i = 0; i < 2; i++)
#pragma unroll
        for (int j = 0; j < 8; j++)
#pragma unroll
            for (int r = 0; r < 4; r++) acc[i][j][r] = 0.f;

#pragma unroll
    for (int ks = 0; ks < 4; ks++) {
        const int kb = ks * 16;
        unsigned a[2][4], b[8][2];
#pragma unroll
        for (int mt = 0; mt < 2; mt++) {
            const int r0 = wm * 32 + mt * 16 + g;
            a[mt][0] = *(const unsigned*)&As[r0    ][kb + 2 * qd];
            a[mt][1] = *(const unsigned*)&As[r0 + 8][kb + 2 * qd];
            a[mt][2] = *(const unsigned*)&As[r0    ][kb + 2 * qd + 8];
            a[mt][3] = *(const unsigned*)&As[r0 + 8][kb + 2 * qd + 8];
        }
#pragma unroll
        for (int nt = 0; nt < 8; nt++) {
            const int c0 = wn * 64 + nt * 8 + g;
            b[nt][0] = *(const unsigned*)&Bs[c0][kb + 2 * qd];
            b[nt][1] = *(const unsigned*)&Bs[c0][kb + 2 * qd + 8];
        }
#pragma unroll
        for (int mt = 0; mt < 2; mt++)
#pragma unroll
            for (int nt = 0; nt < 8; nt++)
                mma_f16(acc[mt][nt], a[mt], b[nt]);
    }

#pragma unroll
    for (int mt = 0; mt < 2; mt++) {
#pragma unroll
        for (int nt = 0; nt < 8; nt++) {
            const int lcc = wn * 64 + nt * 8 + 2 * qd;
            const bool z0 = (Mc[lcc] == 0), z1 = (Mc[lcc + 1] == 0);
#pragma unroll
            for (int half = 0; half < 2; half++) {
                const int lr = wm * 32 + mt * 16 + g + half * 8;
                const float m = Sm[lr], inv = Si[lr];
                float s0 = z0 ? -1e10f : acc[mt][nt][2 * half]     * 0.125f;
                float s1 = z1 ? -1e10f : acc[mt][nt][2 * half + 1] * 0.125f;
                float2 v;
                v.x = __expf(s0 - m) * inv;
                v.y = __expf(s1 - m) * inv;
                *(float2*)&C[(size_t)(brow + lr) * SDIM + bcol + lcc] = v;
            }
        }
    }
}

// ---------------------------------------------------------------------------
extern "C" void kernel_launch(void* const* d_in, const int* in_sizes, int n_in,
                              void* d_out, int out_size)
{
    const float* query  = (const float*)d_in[0];
    const float* key_in = (const float*)d_in[1];
    const float* value  = (const float*)d_in[2];
    const int*   mask   = (const int*)  d_in[3];
    const float* Wq = (const float*)d_in[4],  *bq = (const float*)d_in[5];
    const float* Wk = (const float*)d_in[6],  *bk = (const float*)d_in[7];
    const float* Wv = (const float*)d_in[8],  *bv = (const float*)d_in[9];
    const float* Wo = (const float*)d_in[10], *bo = (const float*)d_in[11];
    float* out = (float*)d_out;

    float *qbuf, *kbuf, *vbuf, *cbuf;
    float2* sbuf;
    cudaGetSymbolAddress((void**)&qbuf, g_Q);
    cudaGetSymbolAddress((void**)&kbuf, g_K);
    cudaGetSymbolAddress((void**)&vbuf, g_V);
    cudaGetSymbolAddress((void**)&cbuf, g_ctx);
    cudaGetSymbolAddress((void**)&sbuf, g_stats);

    const long long XE = (long long)BDIM * SDIM * HDIM;       // 8,388,608
    float* att = out + XE;                                    // [B,H,S,S]

    const int smem_f = 89088 + SDIM * 4;                      // 97,280
    const int smem_p = 36864 + 2 * 128 * 4 + 128 * 4;         // 38,400
    cudaFuncSetAttribute(flash_attn, cudaFuncAttributeMaxDynamicSharedMemorySize, smem_f);
    cudaFuncSetAttribute(probs_k64, cudaFuncAttributeMaxDynamicSharedMemorySize, smem_p);

    // 1) QKV projections (fp16 MMA), scatter to [B,H,S,Dh]
    const dim3 gp(HDIM / 128, (BDIM * SDIM) / 128, 1);
    gemm128h<1><<<gp, 256>>>(query,  Wq, bq, qbuf, HDIM, HDIM);
    gemm128h<1><<<gp, 256>>>(key_in, Wk, bk, kbuf, HDIM, HDIM);
    gemm128h<1><<<gp, 256>>>(value,  Wv, bv, vbuf, HDIM, HDIM);

    // 2) Flash attention (fp16 core) -> ctx + stats
    flash_attn<<<dim3(SDIM / 128, BDIM * NH), 256, smem_f>>>(mask, cbuf, sbuf);

    // 3) Probs replay (fp16, bitwise-consistent with flash) -> attention output
    probs_k64<<<dim3(SDIM / 128, SDIM / 128, BDIM * NH), 256, smem_p>>>(
        qbuf, kbuf, att, mask, sbuf);

    // 4) Output projection (fp16 MMA) -> x
    gemm128h<0><<<gp, 256>>>(cbuf, Wo, bo, out, HDIM, HDIM);
}

// round 15
// speedup vs baseline: 1.5059x; 1.0324x over previous
#include <cuda_runtime.h>
#include <cuda_fp16.h>
#include <cstdint>

#define BDIM 4
#define SDIM 2048
#define HDIM 1024
#define NH   16
#define DH   64

// Scratch (device globals: no allocation allowed in kernel_launch)
__device__ float g_Q[(size_t)BDIM * NH * SDIM * DH];
__device__ float g_K[(size_t)BDIM * NH * SDIM * DH];
__device__ float g_V[(size_t)BDIM * NH * SDIM * DH];
__device__ float g_ctx[(size_t)BDIM * SDIM * HDIM];
__device__ float2 g_stats[(size_t)BDIM * NH * SDIM];   // (row_max, 1/row_sum)

// ---------------------------------------------------------------------------
__device__ __forceinline__ void mma_f16(float* c, const unsigned* a,
                                        const unsigned* b) {
    asm volatile(
        "mma.sync.aligned.m16n8k16.row.col.f32.f16.f16.f32 "
        "{%0,%1,%2,%3}, {%4,%5,%6,%7}, {%8,%9}, {%0,%1,%2,%3};\n"
        : "+f"(c[0]), "+f"(c[1]), "+f"(c[2]), "+f"(c[3])
        : "r"(a[0]), "r"(a[1]), "r"(a[2]), "r"(a[3]), "r"(b[0]), "r"(b[1]));
}
__device__ __forceinline__ uint2 f4_to_h4(float4 v) {
    __half2 lo = __floats2half2_rn(v.x, v.y);
    __half2 hi = __floats2half2_rn(v.z, v.w);
    uint2 r;
    r.x = *(unsigned*)&lo;
    r.y = *(unsigned*)&hi;
    return r;
}
__device__ __forceinline__ unsigned h2u(__half2 h) { return *(unsigned*)&h; }

// ---------------------------------------------------------------------------
// Dense GEMM (fp16 operands, fp32 accum): C = A[M,K] @ B[N,K]^T + bias.
// MODE 0: direct row-major C. MODE 1: scatter to [B,H,S,Dh].
// Block 128x128, BK=32, 256 threads, 8 warps (4m x 2n), warp tile 32x64.
// ---------------------------------------------------------------------------
template <int MODE>
__global__ void __launch_bounds__(256, 2) gemm128h(
    const float* __restrict__ A, const float* __restrict__ Bm,
    const float* __restrict__ bias, float* __restrict__ C,
    int K, int ldc)
{
    __shared__ __half As[2][128][40];
    __shared__ __half Bs[2][128][40];

    const int tid  = threadIdx.x;
    const int wid  = tid >> 5, lane = tid & 31;
    const int wm   = wid >> 1, wn = wid & 1;
    const int g    = lane >> 2, qd = lane & 3;
    const int brow = blockIdx.y * 128;
    const int bcol = blockIdx.x * 128;

    const int lr = tid >> 1;          // 0..127
    const int lc = (tid & 1) * 16;    // 0 or 16

    float acc[2][8][4];
#pragma unroll
    for (int i = 0; i < 2; i++)
#pragma unroll
        for (int j = 0; j < 8; j++)
#pragma unroll
            for (int r = 0; r < 4; r++) acc[i][j][r] = 0.f;

    const float* Ap = A  + (size_t)(brow + lr) * K + lc;
    const float* Bp = Bm + (size_t)(bcol + lr) * K + lc;

    float4 pa[4], pb[4];
#pragma unroll
    for (int p = 0; p < 4; p++) {
        pa[p] = *(const float4*)(Ap + 4 * p);
        pb[p] = *(const float4*)(Bp + 4 * p);
    }
#pragma unroll
    for (int p = 0; p < 4; p++) {
        *(uint2*)&As[0][lr][lc + 4 * p] = f4_to_h4(pa[p]);
        *(uint2*)&Bs[0][lr][lc + 4 * p] = f4_to_h4(pb[p]);
    }
    __syncthreads();

    int buf = 0;
    for (int k0 = 0; k0 < K; k0 += 32, buf ^= 1) {
        const bool more = (k0 + 32) < K;
        if (more) {
#pragma unroll
            for (int p = 0; p < 4; p++) {
                pa[p] = *(const float4*)(Ap + k0 + 32 + 4 * p);
                pb[p] = *(const float4*)(Bp + k0 + 32 + 4 * p);
            }
        }

#pragma unroll
        for (int ks = 0; ks < 2; ks++) {
            const int kb = ks * 16;
            unsigned a[2][4], b[8][2];
#pragma unroll
            for (int mt = 0; mt < 2; mt++) {
                const int r0 = wm * 32 + mt * 16 + g;
                a[mt][0] = *(const unsigned*)&As[buf][r0    ][kb + 2 * qd];
                a[mt][1] = *(const unsigned*)&As[buf][r0 + 8][kb + 2 * qd];
                a[mt][2] = *(const unsigned*)&As[buf][r0    ][kb + 2 * qd + 8];
                a[mt][3] = *(const unsigned*)&As[buf][r0 + 8][kb + 2 * qd + 8];
            }
#pragma unroll
            for (int nt = 0; nt < 8; nt++) {
                const int c0 = wn * 64 + nt * 8 + g;
                b[nt][0] = *(const unsigned*)&Bs[buf][c0][kb + 2 * qd];
                b[nt][1] = *(const unsigned*)&Bs[buf][c0][kb + 2 * qd + 8];
            }
#pragma unroll
            for (int mt = 0; mt < 2; mt++)
#pragma unroll
                for (int nt = 0; nt < 8; nt++)
                    mma_f16(acc[mt][nt], a[mt], b[nt]);
        }

        if (more) {
#pragma unroll
            for (int p = 0; p < 4; p++) {
                *(uint2*)&As[buf ^ 1][lr][lc + 4 * p] = f4_to_h4(pa[p]);
                *(uint2*)&Bs[buf ^ 1][lr][lc + 4 * p] = f4_to_h4(pb[p]);
            }
            __syncthreads();
        }
    }

#pragma unroll
    for (int mt = 0; mt < 2; mt++) {
#pragma unroll
        for (int nt = 0; nt < 8; nt++) {
            const int cc = bcol + wn * 64 + nt * 8 + 2 * qd;
            const float bx = bias[cc], by = bias[cc + 1];
#pragma unroll
            for (int half = 0; half < 2; half++) {
                const int r = brow + wm * 32 + mt * 16 + g + half * 8;
                float2 v;
                v.x = acc[mt][nt][2 * half]     + bx;
                v.y = acc[mt][nt][2 * half + 1] + by;
                if (MODE == 1) {
                    const int b_ = r / SDIM, s = r % SDIM;
                    const int h  = cc / DH,  d = cc % DH;
                    *(float2*)&C[(((size_t)(b_ * NH + h)) * SDIM + s) * DH + d] = v;
                } else {
                    *(float2*)&C[(size_t)r * ldc + cc] = v;
                }
            }
        }
    }
}

// ---------------------------------------------------------------------------
// Flash attention, fp16 core, P KEPT IN REGISTERS:
// the score-MMA accumulator layout (rows g/g+8, cols 2qd..) IS the fp16
// A-fragment layout for the PV MMA, so exp() results are packed to half2
// registers and fed straight into PV -- no P smem round trip.
// ---------------------------------------------------------------------------
__global__ void __launch_bounds__(256, 1) flash_attn(
    const int* __restrict__ mask, float* __restrict__ ctx,
    float2* __restrict__ stats)
{
    extern __shared__ char smem_raw[];
    __half (*Qs)[72]  = (__half(*)[72])smem_raw;                    // 128 x 64
    __half (*Ks)[72]  = (__half(*)[72])(smem_raw + 18432);          // 128 x 64
    __half (*Vs)[136] = (__half(*)[136])(smem_raw + 36864);         // 64(d) x 128(k)
    int*    Ms        = (int*)(smem_raw + 54272);                   // 2048

    const int bh = blockIdx.y;
    const int q0 = blockIdx.x * 128;
    const int b_ = bh / NH, h = bh % NH;
    const int tid = threadIdx.x, wid = tid >> 5, lane = tid & 31;
    const int g = lane >> 2, qd = lane & 3;
    const int r0 = wid * 16 + g;

    const float* Qg = g_Q + ((size_t)bh * SDIM + q0) * DH;
    const float* Kg = g_K + (size_t)bh * SDIM * DH;
    const float* Vg = g_V + (size_t)bh * SDIM * DH;

    // Stage Q (fp16) + mask
#pragma unroll
    for (int i = 0; i < 8; i++) {
        const int idx = tid + i * 256;
        const int r = idx >> 4, c = (idx & 15) * 4;
        *(uint2*)&Qs[r][c] = f4_to_h4(*(const float4*)(Qg + (size_t)r * DH + c));
    }
    for (int i = tid; i < SDIM / 4; i += 256)
        ((int4*)Ms)[i] = ((const int4*)(mask + b_ * SDIM))[i];

    float m_lo = -1e30f, m_hi = -1e30f, s_lo = 0.f, s_hi = 0.f;
    float acc_o[8][4];
#pragma unroll
    for (int j = 0; j < 8; j++)
#pragma unroll
        for (int r = 0; r < 4; r++) acc_o[j][r] = 0.f;

    const int r2 = tid >> 4;            // 0..15
    const int vc = (tid & 15) * 4;      // 0..60

    for (int kt = 0; kt < SDIM / 128; kt++) {
        const int kb0 = kt * 128;
        __syncthreads();   // prev chunk consumed (and Q/mask ready on iter 0)

        // K chunk -> Ks [k][d] fp16
#pragma unroll
        for (int i = 0; i < 8; i++) {
            const int idx = tid + i * 256;
            const int r = idx >> 4, c = (idx & 15) * 4;
            *(uint2*)&Ks[r][c] = f4_to_h4(*(const float4*)(Kg + (size_t)(kb0 + r) * DH + c));
        }
        // V chunk -> Vs TRANSPOSED [d][k] fp16 (half2 per k-pair)
#pragma unroll
        for (int i = 0; i < 4; i++) {
            const int k0 = 2 * (r2 + i * 16);
            float4 f0 = *(const float4*)(Vg + (size_t)(kb0 + k0    ) * DH + vc);
            float4 f1 = *(const float4*)(Vg + (size_t)(kb0 + k0 + 1) * DH + vc);
            *(__half2*)&Vs[vc + 0][k0] = __floats2half2_rn(f0.x, f1.x);
            *(__half2*)&Vs[vc + 1][k0] = __floats2half2_rn(f0.y, f1.y);
            *(__half2*)&Vs[vc + 2][k0] = __floats2half2_rn(f0.z, f1.z);
            *(__half2*)&Vs[vc + 3][k0] = __floats2half2_rn(f0.w, f1.w);
        }
        __syncthreads();

        // ---- scores: 16 x 128 per warp, fp16 k16 x 4 steps ----
        float sacc[16][4];
#pragma unroll
        for (int j = 0; j < 16; j++)
#pragma unroll
            for (int r = 0; r < 4; r++) sacc[j][r] = 0.f;

#pragma unroll
        for (int ks = 0; ks < 4; ks++) {
            const int kb = ks * 16;
            unsigned a[4], b[16][2];
            a[0] = *(const unsigned*)&Qs[r0    ][kb + 2 * qd];
            a[1] = *(const unsigned*)&Qs[r0 + 8][kb + 2 * qd];
            a[2] = *(const unsigned*)&Qs[r0    ][kb + 2 * qd + 8];
            a[3] = *(const unsigned*)&Qs[r0 + 8][kb + 2 * qd + 8];
#pragma unroll
            for (int nt = 0; nt < 16; nt++) {
                const int c0 = nt * 8 + g;
                b[nt][0] = *(const unsigned*)&Ks[c0][kb + 2 * qd];
                b[nt][1] = *(const unsigned*)&Ks[c0][kb + 2 * qd + 8];
            }
#pragma unroll
            for (int nt = 0; nt < 16; nt++)
                mma_f16(sacc[nt], a, b[nt]);
        }

        // ---- mask + scale + chunk max ----
        float cm_lo = -1e30f, cm_hi = -1e30f;
#pragma unroll
        for (int nt = 0; nt < 16; nt++) {
            const int c0 = kb0 + nt * 8 + 2 * qd;
            const bool z0 = (Ms[c0] == 0), z1 = (Ms[c0 + 1] == 0);
            float s0 = z0 ? -1e10f : sacc[nt][0] * 0.125f;
            float s1 = z1 ? -1e10f : sacc[nt][1] * 0.125f;
            float s2 = z0 ? -1e10f : sacc[nt][2] * 0.125f;
            float s3 = z1 ? -1e10f : sacc[nt][3] * 0.125f;
            sacc[nt][0] = s0; sacc[nt][1] = s1;
            sacc[nt][2] = s2; sacc[nt][3] = s3;
            cm_lo = fmaxf(cm_lo, fmaxf(s0, s1));
            cm_hi = fmaxf(cm_hi, fmaxf(s2, s3));
        }
#pragma unroll
        for (int o = 1; o <= 2; o <<= 1) {
            cm_lo = fmaxf(cm_lo, __shfl_xor_sync(0xffffffffu, cm_lo, o));
            cm_hi = fmaxf(cm_hi, __shfl_xor_sync(0xffffffffu, cm_hi, o));
        }

        const float mn_lo = fmaxf(m_lo, cm_lo), mn_hi = fmaxf(m_hi, cm_hi);
        const float rl = __expf(m_lo - mn_lo), rh = __expf(m_hi - mn_hi);

        // ---- exp (fp32 sums), pack P to half2 REGISTERS ----
        unsigned ph_lo[16], ph_hi[16];
        float ps_lo = 0.f, ps_hi = 0.f;
#pragma unroll
        for (int nt = 0; nt < 16; nt++) {
            const float p0 = __expf(sacc[nt][0] - mn_lo);
            const float p1 = __expf(sacc[nt][1] - mn_lo);
            const float p2 = __expf(sacc[nt][2] - mn_hi);
            const float p3 = __expf(sacc[nt][3] - mn_hi);
            ps_lo += p0 + p1; ps_hi += p2 + p3;
            ph_lo[nt] = h2u(__floats2half2_rn(p0, p1));
            ph_hi[nt] = h2u(__floats2half2_rn(p2, p3));
        }
#pragma unroll
        for (int o = 1; o <= 2; o <<= 1) {
            ps_lo += __shfl_xor_sync(0xffffffffu, ps_lo, o);
            ps_hi += __shfl_xor_sync(0xffffffffu, ps_hi, o);
        }
        s_lo = s_lo * rl + ps_lo;
        s_hi = s_hi * rh + ps_hi;
        m_lo = mn_lo; m_hi = mn_hi;

        // rescale O accumulators
#pragma unroll
        for (int nt = 0; nt < 8; nt++) {
            acc_o[nt][0] *= rl; acc_o[nt][1] *= rl;
            acc_o[nt][2] *= rh; acc_o[nt][3] *= rh;
        }

        // ---- PV: O += P(16x128) @ V(128x64); P fragments from registers ----
#pragma unroll
        for (int ks = 0; ks < 8; ks++) {
            const int kb = ks * 16;
            unsigned a[4], b[8][2];
            a[0] = ph_lo[2 * ks];
            a[1] = ph_hi[2 * ks];
            a[2] = ph_lo[2 * ks + 1];
            a[3] = ph_hi[2 * ks + 1];
#pragma unroll
            for (int nt = 0; nt < 8; nt++) {
                const int c0 = nt * 8 + g;
                b[nt][0] = *(const unsigned*)&Vs[c0][kb + 2 * qd];
                b[nt][1] = *(const unsigned*)&Vs[c0][kb + 2 * qd + 8];
            }
#pragma unroll
            for (int nt = 0; nt < 8; nt++)
                mma_f16(acc_o[nt], a, b[nt]);
        }
    }

    // ---- epilogue: normalize, write ctx + stats ----
    const float inv_lo = 1.f / s_lo, inv_hi = 1.f / s_hi;
#pragma unroll
    for (int nt = 0; nt < 8; nt++) {
        const int d = h * DH + nt * 8 + 2 * qd;
        float2 v0, v1;
        v0.x = acc_o[nt][0] * inv_lo; v0.y = acc_o[nt][1] * inv_lo;
        v1.x = acc_o[nt][2] * inv_hi; v1.y = acc_o[nt][3] * inv_hi;
        *(float2*)&ctx[((size_t)(b_ * SDIM + q0 + r0    )) * HDIM + d] = v0;
        *(float2*)&ctx[((size_t)(b_ * SDIM + q0 + r0 + 8)) * HDIM + d] = v1;
    }
    if (qd == 0) {
        stats[(size_t)bh * SDIM + q0 + r0    ] = make_float2(m_lo, inv_lo);
        stats[(size_t)bh * SDIM + q0 + r0 + 8] = make_float2(m_hi, inv_hi);
    }
}

// ---------------------------------------------------------------------------
// Probs replay (fp16 MMA, IDENTICAL sequence to flash scores): recompute
// E tile, mask, p = exp(s - m) * inv with flash stats; streaming-store probs.
// Block tile 128x128, 2 CTAs/SM. 8 warps (4m x 2n), warp tile 32x64.
// ---------------------------------------------------------------------------
__global__ void __launch_bounds__(256, 2) probs_k64(
    const float* __restrict__ Qg, const float* __restrict__ Kg,
    float* __restrict__ att, const int* __restrict__ mask,
    const float2* __restrict__ stats)
{
    extern __shared__ char smem_raw[];
    __half (*As)[72] = (__half(*)[72])smem_raw;                     // 128 x 64
    __half (*Bs)[72] = (__half(*)[72])(smem_raw + 18432);           // 128 x 64
    float* Sm = (float*)(smem_raw + 36864);                         // 128 row max
    float* Si = Sm + 128;                                           // 128 row inv
    int*   Mc = (int*)(Si + 128);                                   // 128 col mask

    const int bh = blockIdx.z;
    const float* A = Qg + (size_t)bh * SDIM * DH;
    const float* B = Kg + (size_t)bh * SDIM * DH;
    float* C = att + (size_t)bh * SDIM * SDIM;

    const int tid  = threadIdx.x;
    const int wid  = tid >> 5, lane = tid & 31;
    const int wm   = wid >> 1, wn = wid & 1;
    const int g    = lane >> 2, qd = lane & 3;
    const int brow = blockIdx.y * 128;
    const int bcol = blockIdx.x * 128;
    const int b_   = bh / NH;

#pragma unroll
    for (int i = 0; i < 8; i++) {
        const int idx = tid + i * 256;
        const int r = idx >> 4, c = (idx & 15) * 4;
        *(uint2*)&As[r][c] = f4_to_h4(*(const float4*)(A + (size_t)(brow + r) * DH + c));
        *(uint2*)&Bs[r][c] = f4_to_h4(*(const float4*)(B + (size_t)(bcol + r) * DH + c));
    }
    if (tid < 128) {
        const float2 st = stats[(size_t)bh * SDIM + brow + tid];
        Sm[tid] = st.x; Si[tid] = st.y;
    } else {
        Mc[tid - 128] = mask[b_ * SDIM + bcol + tid - 128];
    }
    __syncthreads();

    float acc[2][8][4];
#pragma unroll
    for (int i = 0; i < 2; i++)
#pragma unroll
        for (int j = 0; j < 8; j++)
#pragma unroll
            for (int r = 0; r < 4; r++) acc[i][j][r] = 0.f;

#pragma unroll
    for (int ks = 0; ks < 4; ks++) {
        const int kb = ks * 16;
        unsigned a[2][4], b[8][2];
#pragma unroll
        for (int mt = 0; mt < 2; mt++) {
            const int r0 = wm * 32 + mt * 16 + g;
            a[mt][0] = *(const unsigned*)&As[r0    ][kb + 2 * qd];
            a[mt][1] = *(const unsigned*)&As[r0 + 8][kb + 2 * qd];
            a[mt][2] = *(const unsigned*)&As[r0    ][kb + 2 * qd + 8];
            a[mt][3] = *(const unsigned*)&As[r0 + 8][kb + 2 * qd + 8];
        }
#pragma unroll
        for (int nt = 0; nt < 8; nt++) {
            const int c0 = wn * 64 + nt * 8 + g;
            b[nt][0] = *(const unsigned*)&Bs[c0][kb + 2 * qd];
            b[nt][1] = *(const unsigned*)&Bs[c0][kb + 2 * qd + 8];
        }
#pragma unroll
        for (int mt = 0; mt < 2; mt++)
#pragma unroll
            for (int nt = 0; nt < 8; nt++)
                mma_f16(acc[mt][nt], a[mt], b[nt]);
    }

#pragma unroll
    for (int mt = 0; mt < 2; mt++) {
#pragma unroll
        for (int nt = 0; nt < 8; nt++) {
            const int lcc = wn * 64 + nt * 8 + 2 * qd;
            const bool z0 = (Mc[lcc] == 0), z1 = (Mc[lcc + 1] == 0);
#pragma unroll
            for (int half = 0; half < 2; half++) {
                const int lr = wm * 32 + mt * 16 + g + half * 8;
                const float m = Sm[lr], inv = Si[lr];
                float s0 = z0 ? -1e10f : acc[mt][nt][2 * half]     * 0.125f;
                float s1 = z1 ? -1e10f : acc[mt][nt][2 * half + 1] * 0.125f;
                float2 v;
                v.x = __expf(s0 - m) * inv;
                v.y = __expf(s1 - m) * inv;
                __stcs((float2*)&C[(size_t)(brow + lr) * SDIM + bcol + lcc], v);
            }
        }
    }
}

// ---------------------------------------------------------------------------
extern "C" void kernel_launch(void* const* d_in, const int* in_sizes, int n_in,
                              void* d_out, int out_size)
{
    const float* query  = (const float*)d_in[0];
    const float* key_in = (const float*)d_in[1];
    const float* value  = (const float*)d_in[2];
    const int*   mask   = (const int*)  d_in[3];
    const float* Wq = (const float*)d_in[4],  *bq = (const float*)d_in[5];
    const float* Wk = (const float*)d_in[6],  *bk = (const float*)d_in[7];
    const float* Wv = (const float*)d_in[8],  *bv = (const float*)d_in[9];
    const float* Wo = (const float*)d_in[10], *bo = (const float*)d_in[11];
    float* out = (float*)d_out;

    float *qbuf, *kbuf, *vbuf, *cbuf;
    float2* sbuf;
    cudaGetSymbolAddress((void**)&qbuf, g_Q);
    cudaGetSymbolAddress((void**)&kbuf, g_K);
    cudaGetSymbolAddress((void**)&vbuf, g_V);
    cudaGetSymbolAddress((void**)&cbuf, g_ctx);
    cudaGetSymbolAddress((void**)&sbuf, g_stats);

    const long long XE = (long long)BDIM * SDIM * HDIM;       // 8,388,608
    float* att = out + XE;                                    // [B,H,S,S]

    const int smem_f = 54272 + SDIM * 4;                      // 62,464
    const int smem_p = 36864 + 2 * 128 * 4 + 128 * 4;         // 38,400
    cudaFuncSetAttribute(flash_attn, cudaFuncAttributeMaxDynamicSharedMemorySize, smem_f);
    cudaFuncSetAttribute(probs_k64, cudaFuncAttributeMaxDynamicSharedMemorySize, smem_p);

    // 1) QKV projections (fp16 MMA), scatter to [B,H,S,Dh]
    const dim3 gp(HDIM / 128, (BDIM * SDIM) / 128, 1);
    gemm128h<1><<<gp, 256>>>(query,  Wq, bq, qbuf, HDIM, HDIM);
    gemm128h<1><<<gp, 256>>>(key_in, Wk, bk, kbuf, HDIM, HDIM);
    gemm128h<1><<<gp, 256>>>(value,  Wv, bv, vbuf, HDIM, HDIM);

    // 2) Flash attention (fp16 core, register-resident P) -> ctx + stats
    flash_attn<<<dim3(SDIM / 128, BDIM * NH), 256, smem_f>>>(mask, cbuf, sbuf);

    // 3) Probs replay (fp16, bitwise-consistent with flash) -> attention output
    probs_k64<<<dim3(SDIM / 128, SDIM / 128, BDIM * NH), 256, smem_p>>>(
        qbuf, kbuf, att, mask, sbuf);

    // 4) Output projection (fp16 MMA) -> x
    gemm128h<0><<<gp, 256>>>(cbuf, Wo, bo, out, HDIM, HDIM);
}

// round 16
// speedup vs baseline: 1.5195x; 1.0090x over previous
#include <cuda_runtime.h>
#include <cuda_fp16.h>
#include <cstdint>

#define BDIM 4
#define SDIM 2048
#define HDIM 1024
#define NH   16
#define DH   64

// Scratch (device globals: no allocation allowed in kernel_launch)
__device__ float g_Q[(size_t)BDIM * NH * SDIM * DH];
__device__ float g_K[(size_t)BDIM * NH * SDIM * DH];
__device__ float g_V[(size_t)BDIM * NH * SDIM * DH];
__device__ float g_ctx[(size_t)BDIM * SDIM * HDIM];
__device__ float2 g_stats[(size_t)BDIM * NH * SDIM];   // (row_max, 1/row_sum)

// ---------------------------------------------------------------------------
__device__ __forceinline__ void mma_f16(float* c, const unsigned* a,
                                        const unsigned* b) {
    asm volatile(
        "mma.sync.aligned.m16n8k16.row.col.f32.f16.f16.f32 "
        "{%0,%1,%2,%3}, {%4,%5,%6,%7}, {%8,%9}, {%0,%1,%2,%3};\n"
        : "+f"(c[0]), "+f"(c[1]), "+f"(c[2]), "+f"(c[3])
        : "r"(a[0]), "r"(a[1]), "r"(a[2]), "r"(a[3]), "r"(b[0]), "r"(b[1]));
}
__device__ __forceinline__ void ldsm_x4(unsigned* r, unsigned addr) {
    asm volatile(
        "ldmatrix.sync.aligned.m8n8.x4.shared.b16 {%0,%1,%2,%3}, [%4];"
        : "=r"(r[0]), "=r"(r[1]), "=r"(r[2]), "=r"(r[3]) : "r"(addr));
}
__device__ __forceinline__ uint2 f4_to_h4(float4 v) {
    __half2 lo = __floats2half2_rn(v.x, v.y);
    __half2 hi = __floats2half2_rn(v.z, v.w);
    uint2 r;
    r.x = *(unsigned*)&lo;
    r.y = *(unsigned*)&hi;
    return r;
}
__device__ __forceinline__ unsigned h2u(__half2 h) { return *(unsigned*)&h; }

// ---------------------------------------------------------------------------
// Dense GEMM (fp16 operands, fp32 accum): C = A[M,K] @ B[N,K]^T + bias.
// MODE 0: direct row-major C. MODE 1: scatter to [B,H,S,Dh].
// Block 128x128, BK=32, 256 threads, 8 warps (4m x 2n), warp tile 32x64.
// ---------------------------------------------------------------------------
template <int MODE>
__global__ void __launch_bounds__(256, 2) gemm128h(
    const float* __restrict__ A, const float* __restrict__ Bm,
    const float* __restrict__ bias, float* __restrict__ C,
    int K, int ldc)
{
    __shared__ __half As[2][128][40];
    __shared__ __half Bs[2][128][40];

    const int tid  = threadIdx.x;
    const int wid  = tid >> 5, lane = tid & 31;
    const int wm   = wid >> 1, wn = wid & 1;
    const int g    = lane >> 2, qd = lane & 3;
    const int brow = blockIdx.y * 128;
    const int bcol = blockIdx.x * 128;

    const int lr = tid >> 1;          // 0..127
    const int lc = (tid & 1) * 16;    // 0 or 16

    float acc[2][8][4];
#pragma unroll
    for (int i = 0; i < 2; i++)
#pragma unroll
        for (int j = 0; j < 8; j++)
#pragma unroll
            for (int r = 0; r < 4; r++) acc[i][j][r] = 0.f;

    const float* Ap = A  + (size_t)(brow + lr) * K + lc;
    const float* Bp = Bm + (size_t)(bcol + lr) * K + lc;

    float4 pa[4], pb[4];
#pragma unroll
    for (int p = 0; p < 4; p++) {
        pa[p] = *(const float4*)(Ap + 4 * p);
        pb[p] = *(const float4*)(Bp + 4 * p);
    }
#pragma unroll
    for (int p = 0; p < 4; p++) {
        *(uint2*)&As[0][lr][lc + 4 * p] = f4_to_h4(pa[p]);
        *(uint2*)&Bs[0][lr][lc + 4 * p] = f4_to_h4(pb[p]);
    }
    __syncthreads();

    int buf = 0;
    for (int k0 = 0; k0 < K; k0 += 32, buf ^= 1) {
        const bool more = (k0 + 32) < K;
        if (more) {
#pragma unroll
            for (int p = 0; p < 4; p++) {
                pa[p] = *(const float4*)(Ap + k0 + 32 + 4 * p);
                pb[p] = *(const float4*)(Bp + k0 + 32 + 4 * p);
            }
        }

#pragma unroll
        for (int ks = 0; ks < 2; ks++) {
            const int kb = ks * 16;
            unsigned a[2][4], b[8][2];
#pragma unroll
            for (int mt = 0; mt < 2; mt++) {
                const int r0 = wm * 32 + mt * 16 + g;
                a[mt][0] = *(const unsigned*)&As[buf][r0    ][kb + 2 * qd];
                a[mt][1] = *(const unsigned*)&As[buf][r0 + 8][kb + 2 * qd];
                a[mt][2] = *(const unsigned*)&As[buf][r0    ][kb + 2 * qd + 8];
                a[mt][3] = *(const unsigned*)&As[buf][r0 + 8][kb + 2 * qd + 8];
            }
#pragma unroll
            for (int nt = 0; nt < 8; nt++) {
                const int c0 = wn * 64 + nt * 8 + g;
                b[nt][0] = *(const unsigned*)&Bs[buf][c0][kb + 2 * qd];
                b[nt][1] = *(const unsigned*)&Bs[buf][c0][kb + 2 * qd + 8];
            }
#pragma unroll
            for (int mt = 0; mt < 2; mt++)
#pragma unroll
                for (int nt = 0; nt < 8; nt++)
                    mma_f16(acc[mt][nt], a[mt], b[nt]);
        }

        if (more) {
#pragma unroll
            for (int p = 0; p < 4; p++) {
                *(uint2*)&As[buf ^ 1][lr][lc + 4 * p] = f4_to_h4(pa[p]);
                *(uint2*)&Bs[buf ^ 1][lr][lc + 4 * p] = f4_to_h4(pb[p]);
            }
            __syncthreads();
        }
    }

#pragma unroll
    for (int mt = 0; mt < 2; mt++) {
#pragma unroll
        for (int nt = 0; nt < 8; nt++) {
            const int cc = bcol + wn * 64 + nt * 8 + 2 * qd;
            const float bx = bias[cc], by = bias[cc + 1];
#pragma unroll
            for (int half = 0; half < 2; half++) {
                const int r = brow + wm * 32 + mt * 16 + g + half * 8;
                float2 v;
                v.x = acc[mt][nt][2 * half]     + bx;
                v.y = acc[mt][nt][2 * half + 1] + by;
                if (MODE == 1) {
                    const int b_ = r / SDIM, s = r % SDIM;
                    const int h  = cc / DH,  d = cc % DH;
                    *(float2*)&C[(((size_t)(b_ * NH + h)) * SDIM + s) * DH + d] = v;
                } else {
                    *(float2*)&C[(size_t)r * ldc + cc] = v;
                }
            }
        }
    }
}

// ---------------------------------------------------------------------------
// Flash attention, fp16 core, register-resident P, ldmatrix fragment loads:
//   Q fragments hoisted to registers (loop-invariant);
//   K/V fragments via ldmatrix.m8n8.x4 (4x fewer smem wavefronts).
// ---------------------------------------------------------------------------
__global__ void __launch_bounds__(256, 1) flash_attn(
    const int* __restrict__ mask, float* __restrict__ ctx,
    float2* __restrict__ stats)
{
    extern __shared__ char smem_raw[];
    __half (*Qs)[72]  = (__half(*)[72])smem_raw;                    // 128 x 64
    __half (*Ks)[72]  = (__half(*)[72])(smem_raw + 18432);          // 128 x 64
    __half (*Vs)[136] = (__half(*)[136])(smem_raw + 36864);         // 64(d) x 128(k)
    int*    Ms        = (int*)(smem_raw + 54272);                   // 2048

    const int bh = blockIdx.y;
    const int q0 = blockIdx.x * 128;
    const int b_ = bh / NH, h = bh % NH;
    const int tid = threadIdx.x, wid = tid >> 5, lane = tid & 31;
    const int g = lane >> 2, qd = lane & 3;
    const int r0 = wid * 16 + g;

    const float* Qg = g_Q + ((size_t)bh * SDIM + q0) * DH;
    const float* Kg = g_K + (size_t)bh * SDIM * DH;
    const float* Vg = g_V + (size_t)bh * SDIM * DH;

    // ldmatrix lane addressing: grp selects (tile-n, tile-k) quadrant
    const int grp = lane >> 3, rw = lane & 7;
    const unsigned ks_base = (unsigned)__cvta_generic_to_shared(&Ks[0][0]);
    const unsigned vs_base = (unsigned)__cvta_generic_to_shared(&Vs[0][0]);
    const unsigned off_k = (((grp >> 1) * 8 + rw) * 72  + (grp & 1) * 8) * 2;
    const unsigned off_v = (((grp >> 1) * 8 + rw) * 136 + (grp & 1) * 8) * 2;

    // Stage Q (fp16) + mask
#pragma unroll
    for (int i = 0; i < 8; i++) {
        const int idx = tid + i * 256;
        const int r = idx >> 4, c = (idx & 15) * 4;
        *(uint2*)&Qs[r][c] = f4_to_h4(*(const float4*)(Qg + (size_t)r * DH + c));
    }
    for (int i = tid; i < SDIM / 4; i += 256)
        ((int4*)Ms)[i] = ((const int4*)(mask + b_ * SDIM))[i];
    __syncthreads();

    // Hoist Q fragments (constant across all key chunks)
    unsigned qa[4][4];
#pragma unroll
    for (int ks = 0; ks < 4; ks++) {
        const int kb = ks * 16;
        qa[ks][0] = *(const unsigned*)&Qs[r0    ][kb + 2 * qd];
        qa[ks][1] = *(const unsigned*)&Qs[r0 + 8][kb + 2 * qd];
        qa[ks][2] = *(const unsigned*)&Qs[r0    ][kb + 2 * qd + 8];
        qa[ks][3] = *(const unsigned*)&Qs[r0 + 8][kb + 2 * qd + 8];
    }

    float m_lo = -1e30f, m_hi = -1e30f, s_lo = 0.f, s_hi = 0.f;
    float acc_o[8][4];
#pragma unroll
    for (int j = 0; j < 8; j++)
#pragma unroll
        for (int r = 0; r < 4; r++) acc_o[j][r] = 0.f;

    const int r2 = tid >> 4;            // 0..15
    const int vc = (tid & 15) * 4;      // 0..60

    for (int kt = 0; kt < SDIM / 128; kt++) {
        const int kb0 = kt * 128;
        __syncthreads();   // prev chunk fully consumed

        // K chunk -> Ks [k][d] fp16
#pragma unroll
        for (int i = 0; i < 8; i++) {
            const int idx = tid + i * 256;
            const int r = idx >> 4, c = (idx & 15) * 4;
            *(uint2*)&Ks[r][c] = f4_to_h4(*(const float4*)(Kg + (size_t)(kb0 + r) * DH + c));
        }
        // V chunk -> Vs TRANSPOSED [d][k] fp16 (half2 per k-pair)
#pragma unroll
        for (int i = 0; i < 4; i++) {
            const int k0 = 2 * (r2 + i * 16);
            float4 f0 = *(const float4*)(Vg + (size_t)(kb0 + k0    ) * DH + vc);
            float4 f1 = *(const float4*)(Vg + (size_t)(kb0 + k0 + 1) * DH + vc);
            *(__half2*)&Vs[vc + 0][k0] = __floats2half2_rn(f0.x, f1.x);
            *(__half2*)&Vs[vc + 1][k0] = __floats2half2_rn(f0.y, f1.y);
            *(__half2*)&Vs[vc + 2][k0] = __floats2half2_rn(f0.z, f1.z);
            *(__half2*)&Vs[vc + 3][k0] = __floats2half2_rn(f0.w, f1.w);
        }
        __syncthreads();

        // ---- scores: 16 x 128 per warp; K fragments via ldmatrix.x4 ----
        float sacc[16][4];
#pragma unroll
        for (int j = 0; j < 16; j++)
#pragma unroll
            for (int r = 0; r < 4; r++) sacc[j][r] = 0.f;

#pragma unroll
        for (int ks = 0; ks < 4; ks++) {
            const int kb = ks * 16;
#pragma unroll
            for (int nt2 = 0; nt2 < 8; nt2++) {
                unsigned bf[4];
                ldsm_x4(bf, ks_base + (unsigned)(16 * nt2 * 72 + kb) * 2 + off_k);
                mma_f16(sacc[2 * nt2    ], qa[ks], bf);
                mma_f16(sacc[2 * nt2 + 1], qa[ks], bf + 2);
            }
        }

        // ---- mask + scale + chunk max ----
        float cm_lo = -1e30f, cm_hi = -1e30f;
#pragma unroll
        for (int nt = 0; nt < 16; nt++) {
            const int c0 = kb0 + nt * 8 + 2 * qd;
            const bool z0 = (Ms[c0] == 0), z1 = (Ms[c0 + 1] == 0);
            float s0 = z0 ? -1e10f : sacc[nt][0] * 0.125f;
            float s1 = z1 ? -1e10f : sacc[nt][1] * 0.125f;
            float s2 = z0 ? -1e10f : sacc[nt][2] * 0.125f;
            float s3 = z1 ? -1e10f : sacc[nt][3] * 0.125f;
            sacc[nt][0] = s0; sacc[nt][1] = s1;
            sacc[nt][2] = s2; sacc[nt][3] = s3;
            cm_lo = fmaxf(cm_lo, fmaxf(s0, s1));
            cm_hi = fmaxf(cm_hi, fmaxf(s2, s3));
        }
#pragma unroll
        for (int o = 1; o <= 2; o <<= 1) {
            cm_lo = fmaxf(cm_lo, __shfl_xor_sync(0xffffffffu, cm_lo, o));
            cm_hi = fmaxf(cm_hi, __shfl_xor_sync(0xffffffffu, cm_hi, o));
        }

        const float mn_lo = fmaxf(m_lo, cm_lo), mn_hi = fmaxf(m_hi, cm_hi);
        const float rl = __expf(m_lo - mn_lo), rh = __expf(m_hi - mn_hi);

        // ---- exp (fp32 sums), pack P to half2 registers ----
        unsigned ph_lo[16], ph_hi[16];
        float ps_lo = 0.f, ps_hi = 0.f;
#pragma unroll
        for (int nt = 0; nt < 16; nt++) {
            const float p0 = __expf(sacc[nt][0] - mn_lo);
            const float p1 = __expf(sacc[nt][1] - mn_lo);
            const float p2 = __expf(sacc[nt][2] - mn_hi);
            const float p3 = __expf(sacc[nt][3] - mn_hi);
            ps_lo += p0 + p1; ps_hi += p2 + p3;
            ph_lo[nt] = h2u(__floats2half2_rn(p0, p1));
            ph_hi[nt] = h2u(__floats2half2_rn(p2, p3));
        }
#pragma unroll
        for (int o = 1; o <= 2; o <<= 1) {
            ps_lo += __shfl_xor_sync(0xffffffffu, ps_lo, o);
            ps_hi += __shfl_xor_sync(0xffffffffu, ps_hi, o);
        }
        s_lo = s_lo * rl + ps_lo;
        s_hi = s_hi * rh + ps_hi;
        m_lo = mn_lo; m_hi = mn_hi;

        // rescale O accumulators
#pragma unroll
        for (int nt = 0; nt < 8; nt++) {
            acc_o[nt][0] *= rl; acc_o[nt][1] *= rl;
            acc_o[nt][2] *= rh; acc_o[nt][3] *= rh;
        }

        // ---- PV: O += P(16x128) @ V(128x64); V fragments via ldmatrix.x4 ----
#pragma unroll
        for (int ks = 0; ks < 8; ks++) {
            const int kb = ks * 16;
            unsigned a[4];
            a[0] = ph_lo[2 * ks];
            a[1] = ph_hi[2 * ks];
            a[2] = ph_lo[2 * ks + 1];
            a[3] = ph_hi[2 * ks + 1];
#pragma unroll
            for (int nt2 = 0; nt2 < 4; nt2++) {
                unsigned bf[4];
                ldsm_x4(bf, vs_base + (unsigned)(16 * nt2 * 136 + kb) * 2 + off_v);
                mma_f16(acc_o[2 * nt2    ], a, bf);
                mma_f16(acc_o[2 * nt2 + 1], a, bf + 2);
            }
        }
    }

    // ---- epilogue: normalize, write ctx + stats ----
    const float inv_lo = 1.f / s_lo, inv_hi = 1.f / s_hi;
#pragma unroll
    for (int nt = 0; nt < 8; nt++) {
        const int d = h * DH + nt * 8 + 2 * qd;
        float2 v0, v1;
        v0.x = acc_o[nt][0] * inv_lo; v0.y = acc_o[nt][1] * inv_lo;
        v1.x = acc_o[nt][2] * inv_hi; v1.y = acc_o[nt][3] * inv_hi;
        *(float2*)&ctx[((size_t)(b_ * SDIM + q0 + r0    )) * HDIM + d] = v0;
        *(float2*)&ctx[((size_t)(b_ * SDIM + q0 + r0 + 8)) * HDIM + d] = v1;
    }
    if (qd == 0) {
        stats[(size_t)bh * SDIM + q0 + r0    ] = make_float2(m_lo, inv_lo);
        stats[(size_t)bh * SDIM + q0 + r0 + 8] = make_float2(m_hi, inv_hi);
    }
}

// ---------------------------------------------------------------------------
// Probs replay (fp16 MMA, IDENTICAL sequence to flash scores): recompute
// E tile, mask, p = exp(s - m) * inv with flash stats; streaming-store probs.
// Block tile 128x128, 2 CTAs/SM. 8 warps (4m x 2n), warp tile 32x64.
// ---------------------------------------------------------------------------
__global__ void __launch_bounds__(256, 2) probs_k64(
    const float* __restrict__ Qg, const float* __restrict__ Kg,
    float* __restrict__ att, const int* __restrict__ mask,
    const float2* __restrict__ stats)
{
    extern __shared__ char smem_raw[];
    __half (*As)[72] = (__half(*)[72])smem_raw;                     // 128 x 64
    __half (*Bs)[72] = (__half(*)[72])(smem_raw + 18432);           // 128 x 64
    float* Sm = (float*)(smem_raw + 36864);                         // 128 row max
    float* Si = Sm + 128;                                           // 128 row inv
    int*   Mc = (int*)(Si + 128);                                   // 128 col mask

    const int bh = blockIdx.z;
    const float* A = Qg + (size_t)bh * SDIM * DH;
    const float* B = Kg + (size_t)bh * SDIM * DH;
    float* C = att + (size_t)bh * SDIM * SDIM;

    const int tid  = threadIdx.x;
    const int wid  = tid >> 5, lane = tid & 31;
    const int wm   = wid >> 1, wn = wid & 1;
    const int g    = lane >> 2, qd = lane & 3;
    const int brow = blockIdx.y * 128;
    const int bcol = blockIdx.x * 128;
    const int b_   = bh / NH;

#pragma unroll
    for (int i = 0; i < 8; i++) {
        const int idx = tid + i * 256;
        const int r = idx >> 4, c = (idx & 15) * 4;
        *(uint2*)&As[r][c] = f4_to_h4(*(const float4*)(A + (size_t)(brow + r) * DH + c));
        *(uint2*)&Bs[r][c] = f4_to_h4(*(const float4*)(B + (size_t)(bcol + r) * DH + c));
    }
    if (tid < 128) {
        const float2 st = stats[(size_t)bh * SDIM + brow + tid];
        Sm[tid] = st.x; Si[tid] = st.y;
    } else {
        Mc[tid - 128] = mask[b_ * SDIM + bcol + tid - 128];
    }
    __syncthreads();

    float acc[2][8][4];
#pragma unroll
    for (int i = 0; i < 2; i++)
#pragma unroll
        for (int j = 0; j < 8; j++)
#pragma unroll
            for (int r = 0; r < 4; r++) acc[i][j][r] = 0.f;

#pragma unroll
    for (int ks = 0; ks < 4; ks++) {
        const int kb = ks * 16;
        unsigned a[2][4], b[8][2];
#pragma unroll
        for (int mt = 0; mt < 2; mt++) {
            const int r0 = wm * 32 + mt * 16 + g;
            a[mt][0] = *(const unsigned*)&As[r0    ][kb + 2 * qd];
            a[mt][1] = *(const unsigned*)&As[r0 + 8][kb + 2 * qd];
            a[mt][2] = *(const unsigned*)&As[r0    ][kb + 2 * qd + 8];
            a[mt][3] = *(const unsigned*)&As[r0 + 8][kb + 2 * qd + 8];
        }
#pragma unroll
        for (int nt = 0; nt < 8; nt++) {
            const int c0 = wn * 64 + nt * 8 + g;
            b[nt][0] = *(const unsigned*)&Bs[c0][kb + 2 * qd];
            b[nt][1] = *(const unsigned*)&Bs[c0][kb + 2 * qd + 8];
        }
#pragma unroll
        for (int mt = 0; mt < 2; mt++)
#pragma unroll
            for (int nt = 0; nt < 8; nt++)
                mma_f16(acc[mt][nt], a[mt], b[nt]);
    }

#pragma unroll
    for (int mt = 0; mt < 2; mt++) {
#pragma unroll
        for (int nt = 0; nt < 8; nt++) {
            const int lcc = wn * 64 + nt * 8 + 2 * qd;
            const bool z0 = (Mc[lcc] == 0), z1 = (Mc[lcc + 1] == 0);
#pragma unroll
            for (int half = 0; half < 2; half++) {
                const int lr = wm * 32 + mt * 16 + g + half * 8;
                const float m = Sm[lr], inv = Si[lr];
                float s0 = z0 ? -1e10f : acc[mt][nt][2 * half]     * 0.125f;
                float s1 = z1 ? -1e10f : acc[mt][nt][2 * half + 1] * 0.125f;
                float2 v;
                v.x = __expf(s0 - m) * inv;
                v.y = __expf(s1 - m) * inv;
                __stcs((float2*)&C[(size_t)(brow + lr) * SDIM + bcol + lcc], v);
            }
        }
    }
}

// ---------------------------------------------------------------------------
extern "C" void kernel_launch(void* const* d_in, const int* in_sizes, int n_in,
                              void* d_out, int out_size)
{
    const float* query  = (const float*)d_in[0];
    const float* key_in = (const float*)d_in[1];
    const float* value  = (const float*)d_in[2];
    const int*   mask   = (const int*)  d_in[3];
    const float* Wq = (const float*)d_in[4],  *bq = (const float*)d_in[5];
    const float* Wk = (const float*)d_in[6],  *bk = (const float*)d_in[7];
    const float* Wv = (const float*)d_in[8],  *bv = (const float*)d_in[9];
    const float* Wo = (const float*)d_in[10], *bo = (const float*)d_in[11];
    float* out = (float*)d_out;

    float *qbuf, *kbuf, *vbuf, *cbuf;
    float2* sbuf;
    cudaGetSymbolAddress((void**)&qbuf, g_Q);
    cudaGetSymbolAddress((void**)&kbuf, g_K);
    cudaGetSymbolAddress((void**)&vbuf, g_V);
    cudaGetSymbolAddress((void**)&cbuf, g_ctx);
    cudaGetSymbolAddress((void**)&sbuf, g_stats);

    const long long XE = (long long)BDIM * SDIM * HDIM;       // 8,388,608
    float* att = out + XE;                                    // [B,H,S,S]

    const int smem_f = 54272 + SDIM * 4;                      // 62,464
    const int smem_p = 36864 + 2 * 128 * 4 + 128 * 4;         // 38,400
    cudaFuncSetAttribute(flash_attn, cudaFuncAttributeMaxDynamicSharedMemorySize, smem_f);
    cudaFuncSetAttribute(probs_k64, cudaFuncAttributeMaxDynamicSharedMemorySize, smem_p);

    // 1) QKV projections (fp16 MMA), scatter to [B,H,S,Dh]
    const dim3 gp(HDIM / 128, (BDIM * SDIM) / 128, 1);
    gemm128h<1><<<gp, 256>>>(query,  Wq, bq, qbuf, HDIM, HDIM);
    gemm128h<1><<<gp, 256>>>(key_in, Wk, bk, kbuf, HDIM, HDIM);
    gemm128h<1><<<gp, 256>>>(value,  Wv, bv, vbuf, HDIM, HDIM);

    // 2) Flash attention (fp16 core, ldmatrix fragments) -> ctx + stats
    flash_attn<<<dim3(SDIM / 128, BDIM * NH), 256, smem_f>>>(mask, cbuf, sbuf);

    // 3) Probs replay (fp16, bitwise-consistent with flash) -> attention output
    probs_k64<<<dim3(SDIM / 128, SDIM / 128, BDIM * NH), 256, smem_p>>>(
        qbuf, kbuf, att, mask, sbuf);

    // 4) Output projection (fp16 MMA) -> x
    gemm128h<0><<<gp, 256>>>(cbuf, Wo, bo, out, HDIM, HDIM);
}